// round 1
// baseline (speedup 1.0000x reference)
#include <cuda_runtime.h>
#include <math.h>
#include <stdint.h>

#define NN 100000        // nodes
#define DIN 100
#define DHID 50
#define NRT 474          // doubled relation types
#define NB 5             // bases

// ---------------- scratch (device globals; no allocation allowed) ----------------
__device__ float g_XB1[(size_t)NN * 300];   // [n][b*50+j] for b<5, cols 250..299 = x@root1
__device__ float g_XB2[(size_t)NN * 300];   // same for layer 2 (input h)
__device__ float g_h[(size_t)NN * DHID];
__device__ float g_agg1[(size_t)NN * DHID];
__device__ float g_agg2[(size_t)NN * DHID];
__device__ float g_cnt[NN];
__device__ float g_T1[NRT * DHID];
__device__ float g_T2[NRT * DHID];

// ---------------- zero scratch ----------------
__global__ void k_zero() {
    int stride = gridDim.x * blockDim.x;
    int i0 = blockIdx.x * blockDim.x + threadIdx.x;
    const int total = NN * DHID;
    for (int i = i0; i < total; i += stride) { g_agg1[i] = 0.f; g_agg2[i] = 0.f; }
    for (int i = i0; i < NN; i += stride)    g_cnt[i] = 0.f;
}

// ---------------- per-relation-type tables ----------------
// T1[et][j] = sum_b comp1[et,b] * (relE[et%237] @ basis1[b])[j]
// rel2[et]  = relE[et%237] @ relW            (50)
// T2[et][j] = sum_b comp2[et,b] * (rel2[et] @ basis2[b])[j]
__global__ void k_tables(const float* __restrict__ relE, const float* __restrict__ relW,
                         const float* __restrict__ basis1, const float* __restrict__ comp1,
                         const float* __restrict__ basis2, const float* __restrict__ comp2) {
    int et = blockIdx.x;               // 0..473
    int r = (et < 237) ? et : et - 237;
    __shared__ float sE[DIN];
    __shared__ float sR2[DHID];
    int tid = threadIdx.x;             // 64 threads
    for (int k = tid; k < DIN; k += blockDim.x) sE[k] = relE[r * DIN + k];
    __syncthreads();
    if (tid < DHID) {
        int j = tid;
        float sb[NB] = {0, 0, 0, 0, 0};
        float r2 = 0.f;
        for (int k = 0; k < DIN; k++) {
            float e = sE[k];
#pragma unroll
            for (int b = 0; b < NB; b++)
                sb[b] = fmaf(e, basis1[((size_t)b * DIN + k) * DHID + j], sb[b]);
            r2 = fmaf(e, relW[k * DHID + j], r2);
        }
        float t1 = 0.f;
#pragma unroll
        for (int b = 0; b < NB; b++) t1 = fmaf(comp1[et * NB + b], sb[b], t1);
        g_T1[et * DHID + j] = t1;
        sR2[j] = r2;
    }
    __syncthreads();
    if (tid < DHID) {
        int j = tid;
        float sb[NB] = {0, 0, 0, 0, 0};
        for (int k = 0; k < DHID; k++) {
            float e = sR2[k];
#pragma unroll
            for (int b = 0; b < NB; b++)
                sb[b] = fmaf(e, basis2[((size_t)b * DHID + k) * DHID + j], sb[b]);
        }
        float t2 = 0.f;
#pragma unroll
        for (int b = 0; b < NB; b++) t2 = fmaf(comp2[et * NB + b], sb[b], t2);
        g_T2[et * DHID + j] = t2;
    }
}

// ---------------- node GEMM: XB = A' @ [basis cols (250) | root (50)] ----------------
// A' masks row `target` to zero (layer 1 only). Block: 32 nodes x 300 cols.
// 640 threads; threads 0..599 each compute a 4x4 register tile.
template <int K, int L>
__global__ void k_gemm(const float* __restrict__ A_in, const float* __restrict__ basisW,
                       const float* __restrict__ rootW, const int* __restrict__ targetPtr) {
    extern __shared__ float sm[];
    float* sW = sm;            // K*300
    float* sX = sm + K * 300;  // 32*K
    const float* A = (L == 1) ? A_in : g_h;
    float* outp = (L == 1) ? g_XB1 : g_XB2;

    int tid = threadIdx.x;
    int n0 = blockIdx.x * 32;
    int target = (targetPtr != nullptr) ? *targetPtr : -1;

    for (int idx = tid; idx < K * 300; idx += blockDim.x) {
        int k = idx / 300, c = idx - k * 300;
        float v;
        if (c < 250) {
            int b = c / 50, j = c - b * 50;
            v = basisW[((size_t)b * K + k) * DHID + j];
        } else {
            v = rootW[k * DHID + (c - 250)];
        }
        sW[idx] = v;
    }
    for (int idx = tid; idx < 32 * K; idx += blockDim.x) {
        int i = idx / K, k = idx - i * K;
        int n = n0 + i;
        float v = 0.f;
        if (n < NN && n != target) v = A[(size_t)n * K + k];
        sX[idx] = v;
    }
    __syncthreads();

    if (tid < 600) {
        int ng = tid / 75, cg = tid - ng * 75;
        int i0 = ng * 4, c0 = cg * 4;
        float acc[4][4];
#pragma unroll
        for (int i = 0; i < 4; i++)
#pragma unroll
            for (int j = 0; j < 4; j++) acc[i][j] = 0.f;

#pragma unroll 4
        for (int k = 0; k < K; k++) {
            float4 w = *(const float4*)&sW[k * 300 + c0];
#pragma unroll
            for (int i = 0; i < 4; i++) {
                float a = sX[(i0 + i) * K + k];
                acc[i][0] = fmaf(a, w.x, acc[i][0]);
                acc[i][1] = fmaf(a, w.y, acc[i][1]);
                acc[i][2] = fmaf(a, w.z, acc[i][2]);
                acc[i][3] = fmaf(a, w.w, acc[i][3]);
            }
        }
#pragma unroll
        for (int i = 0; i < 4; i++) {
            int n = n0 + i0 + i;
            if (n < NN)
                *(float4*)&outp[(size_t)n * 300 + c0] =
                    make_float4(acc[i][0], acc[i][1], acc[i][2], acc[i][3]);
        }
    }
}

// ---------------- edge pass: one warp per edge ----------------
// acc[0..49] = T[et] + sum_b comp[et,b] * XB[src, b*50 + :]; red into agg[dst]; count once.
template <int L>
__global__ void k_edge(const int* __restrict__ ei, const int* __restrict__ etype,
                       const float* __restrict__ comp, int E) {
    int w = (blockIdx.x * blockDim.x + threadIdx.x) >> 5;
    if (w >= E) return;
    int lane = threadIdx.x & 31;
    int s = __ldg(ei + w);
    int d = __ldg(ei + E + w);
    int t = __ldg(etype + w);
    const float* T  = (L == 1) ? g_T1  : g_T2;
    const float* XB = (L == 1) ? g_XB1 : g_XB2;
    float* agg      = (L == 1) ? g_agg1 : g_agg2;

    float c0 = __ldg(comp + t * NB + 0);
    float c1 = __ldg(comp + t * NB + 1);
    float c2 = __ldg(comp + t * NB + 2);
    float c3 = __ldg(comp + t * NB + 3);
    float c4 = __ldg(comp + t * NB + 4);

    if (lane < 25) {
        const float2* Tr = (const float2*)(T + t * DHID);
        const float2* xr = (const float2*)(XB + (size_t)s * 300);
        float2 acc = Tr[lane];
        float2 v;
        v = __ldg(xr + lane);       acc.x = fmaf(c0, v.x, acc.x); acc.y = fmaf(c0, v.y, acc.y);
        v = __ldg(xr + 25 + lane);  acc.x = fmaf(c1, v.x, acc.x); acc.y = fmaf(c1, v.y, acc.y);
        v = __ldg(xr + 50 + lane);  acc.x = fmaf(c2, v.x, acc.x); acc.y = fmaf(c2, v.y, acc.y);
        v = __ldg(xr + 75 + lane);  acc.x = fmaf(c3, v.x, acc.x); acc.y = fmaf(c3, v.y, acc.y);
        v = __ldg(xr + 100 + lane); acc.x = fmaf(c4, v.x, acc.x); acc.y = fmaf(c4, v.y, acc.y);
        atomicAdd(((float2*)(agg + (size_t)d * DHID)) + lane, acc);
    }
    if (L == 1 && lane == 31) atomicAdd(&g_cnt[d], 1.0f);
}

// ---------------- layer-1 epilogue: h = agg/cnt + x@root1 + bias1 ----------------
__global__ void k_node1(const float* __restrict__ bias1) {
    int idx = blockIdx.x * blockDim.x + threadIdx.x;
    if (idx >= NN * DHID) return;
    int n = idx / DHID, j = idx - n * DHID;
    float c = fmaxf(g_cnt[n], 1.0f);
    g_h[idx] = g_agg1[idx] / c + g_XB1[(size_t)n * 300 + 250 + j] + bias1[j];
}

// ---------------- output: log_softmax over 50 classes, warp per node ----------------
__global__ void k_out(const float* __restrict__ bias2, float* __restrict__ out) {
    int n = (blockIdx.x * blockDim.x + threadIdx.x) >> 5;
    if (n >= NN) return;
    int lane = threadIdx.x & 31;
    float c = fmaxf(g_cnt[n], 1.0f);
    float vx = -1e30f, vy = -1e30f;
    if (lane < 25) {
        float2 a = ((const float2*)g_agg2)[(size_t)n * 25 + lane];
        float2 r = ((const float2*)(g_XB2 + (size_t)n * 300 + 250))[lane];
        vx = a.x / c + r.x + bias2[2 * lane];
        vy = a.y / c + r.y + bias2[2 * lane + 1];
    }
    float m = fmaxf(vx, vy);
#pragma unroll
    for (int o = 16; o > 0; o >>= 1) m = fmaxf(m, __shfl_xor_sync(0xFFFFFFFFu, m, o));
    float sacc = (lane < 25) ? (expf(vx - m) + expf(vy - m)) : 0.f;
#pragma unroll
    for (int o = 16; o > 0; o >>= 1) sacc += __shfl_xor_sync(0xFFFFFFFFu, sacc, o);
    float ls = logf(sacc);
    if (lane < 25)
        ((float2*)out)[(size_t)n * 25 + lane] = make_float2(vx - m - ls, vy - m - ls);
}

// ---------------- launcher ----------------
extern "C" void kernel_launch(void* const* d_in, const int* in_sizes, int n_in,
                              void* d_out, int out_size) {
    const float* x      = (const float*)d_in[0];
    const int*   ei     = (const int*)d_in[1];
    const int*   etype  = (const int*)d_in[2];
    const int*   tgt    = (const int*)d_in[3];
    const float* relE   = (const float*)d_in[4];
    const float* relW   = (const float*)d_in[5];
    const float* basis1 = (const float*)d_in[6];
    const float* comp1  = (const float*)d_in[7];
    const float* root1  = (const float*)d_in[8];
    const float* bias1  = (const float*)d_in[9];
    const float* basis2 = (const float*)d_in[10];
    const float* comp2  = (const float*)d_in[11];
    const float* root2  = (const float*)d_in[12];
    const float* bias2  = (const float*)d_in[13];
    float* out = (float*)d_out;
    int E = in_sizes[1] / 2;

    constexpr int SM1 = (DIN * 300 + 32 * DIN) * (int)sizeof(float);   // 132.8 KB
    constexpr int SM2 = (DHID * 300 + 32 * DHID) * (int)sizeof(float); //  66.4 KB
    cudaFuncSetAttribute(k_gemm<DIN, 1>, cudaFuncAttributeMaxDynamicSharedMemorySize, SM1);
    cudaFuncSetAttribute(k_gemm<DHID, 2>, cudaFuncAttributeMaxDynamicSharedMemorySize, SM2);

    k_zero<<<4096, 256>>>();
    k_tables<<<NRT, 64>>>(relE, relW, basis1, comp1, basis2, comp2);
    k_gemm<DIN, 1><<<(NN + 31) / 32, 640, SM1>>>(x, basis1, root1, tgt);
    k_edge<1><<<(E + 7) / 8, 256>>>(ei, etype, comp1, E);
    k_node1<<<(NN * DHID + 255) / 256, 256>>>(bias1);
    k_gemm<DHID, 2><<<(NN + 31) / 32, 640, SM2>>>(x /*unused for L2*/, basis2, root2, nullptr);
    k_edge<2><<<(E + 7) / 8, 256>>>(ei, etype, comp2, E);
    k_out<<<(NN + 7) / 8, 256>>>(bias2, out);
}

// round 5
// speedup vs baseline: 1.1944x; 1.1944x over previous
#include <cuda_runtime.h>
#include <cuda_fp16.h>
#include <math.h>
#include <stdint.h>

#define NN 100000        // nodes
#define DIN 100
#define DHID 50
#define NRT 474          // doubled relation types
#define NB 5             // bases

// ---------------- scratch (device globals; no allocation allowed) ----------------
// fp16 gather tables: [n][b*25 + j2] as half2 (250 basis cols), 500 B/row, 50 MB each
__device__ __half2 g_XB1h[(size_t)NN * 125];
__device__ __half2 g_XB2h[(size_t)NN * 125];
__device__ float g_rt1[(size_t)NN * DHID];   // x @ root1 (fp32)
__device__ float g_rt2[(size_t)NN * DHID];   // h @ root2 (fp32)
__device__ float g_h[(size_t)NN * DHID];
__device__ float g_agg1[(size_t)NN * DHID];
__device__ float g_agg2[(size_t)NN * DHID];
__device__ float g_cnt[NN];
__device__ float g_T1[NRT * DHID];
__device__ float g_T2[NRT * DHID];

// ---------------- zero scratch ----------------
__global__ void k_zero() {
    int stride = gridDim.x * blockDim.x;
    int i0 = blockIdx.x * blockDim.x + threadIdx.x;
    const int total = NN * DHID;
    for (int i = i0; i < total; i += stride) { g_agg1[i] = 0.f; g_agg2[i] = 0.f; }
    for (int i = i0; i < NN; i += stride)    g_cnt[i] = 0.f;
}

// ---------------- per-relation-type tables ----------------
__global__ void k_tables(const float* __restrict__ relE, const float* __restrict__ relW,
                         const float* __restrict__ basis1, const float* __restrict__ comp1,
                         const float* __restrict__ basis2, const float* __restrict__ comp2) {
    int et = blockIdx.x;               // 0..473
    int r = (et < 237) ? et : et - 237;
    __shared__ float sE[DIN];
    __shared__ float sR2[DHID];
    int tid = threadIdx.x;             // 64 threads
    for (int k = tid; k < DIN; k += blockDim.x) sE[k] = relE[r * DIN + k];
    __syncthreads();
    if (tid < DHID) {
        int j = tid;
        float sb[NB] = {0, 0, 0, 0, 0};
        float r2 = 0.f;
        for (int k = 0; k < DIN; k++) {
            float e = sE[k];
#pragma unroll
            for (int b = 0; b < NB; b++)
                sb[b] = fmaf(e, basis1[((size_t)b * DIN + k) * DHID + j], sb[b]);
            r2 = fmaf(e, relW[k * DHID + j], r2);
        }
        float t1 = 0.f;
#pragma unroll
        for (int b = 0; b < NB; b++) t1 = fmaf(comp1[et * NB + b], sb[b], t1);
        g_T1[et * DHID + j] = t1;
        sR2[j] = r2;
    }
    __syncthreads();
    if (tid < DHID) {
        int j = tid;
        float sb[NB] = {0, 0, 0, 0, 0};
        for (int k = 0; k < DHID; k++) {
            float e = sR2[k];
#pragma unroll
            for (int b = 0; b < NB; b++)
                sb[b] = fmaf(e, basis2[((size_t)b * DHID + k) * DHID + j], sb[b]);
        }
        float t2 = 0.f;
#pragma unroll
        for (int b = 0; b < NB; b++) t2 = fmaf(comp2[et * NB + b], sb[b], t2);
        g_T2[et * DHID + j] = t2;
    }
}

// ---------------- node GEMM ----------------
// Output columns (logical): [0..49] = root (fp32), [50..299] = basis b=(c-50)/50 (fp16).
// Block: 64 nodes x 300 cols, 640 threads; threads 0..599 compute 8x4 register tiles.
// A in smem k-major; all global stores are pairwise (float2/half2) so region
// boundaries (even) never produce misaligned wide stores.
template <int K, int L>
__global__ void __launch_bounds__(640, 1)
k_gemm(const float* __restrict__ A_in, const float* __restrict__ basisW,
       const float* __restrict__ rootW, const int* __restrict__ targetPtr) {
    extern __shared__ float sm[];
    float* sW = sm;            // [K][300]
    float* sX = sm + K * 300;  // [K][64] (k-major)
    const float* A = (L == 1) ? A_in : g_h;
    __half2* outB = (L == 1) ? g_XB1h : g_XB2h;
    float* outR   = (L == 1) ? g_rt1 : g_rt2;

    int tid = threadIdx.x;
    int n0 = blockIdx.x * 64;
    int target = (L == 1) ? *targetPtr : -1;

    for (int idx = tid; idx < K * 300; idx += 640) {
        int k = idx / 300, c = idx - k * 300;
        float v;
        if (c < 50) {
            v = rootW[k * DHID + c];
        } else {
            int b = (c - 50) / 50, j = (c - 50) - b * 50;
            v = basisW[((size_t)b * K + k) * DHID + j];
        }
        sW[idx] = v;
    }
    for (int idx = tid; idx < K * 64; idx += 640) {
        int i = idx / K, k = idx - i * K;
        int n = n0 + i;
        float v = 0.f;
        if (n < NN && n != target) v = A[(size_t)n * K + k];
        sX[k * 64 + i] = v;
    }
    __syncthreads();

    if (tid < 600) {
        int ng = tid / 75, cg = tid - ng * 75;
        int i0 = ng * 8, c0 = cg * 4;
        float acc[8][4];
#pragma unroll
        for (int i = 0; i < 8; i++)
#pragma unroll
            for (int j = 0; j < 4; j++) acc[i][j] = 0.f;

#pragma unroll 2
        for (int k = 0; k < K; k++) {
            float4 w  = *(const float4*)&sW[k * 300 + c0];
            float4 a0 = *(const float4*)&sX[k * 64 + i0];
            float4 a1 = *(const float4*)&sX[k * 64 + i0 + 4];
            float ar[8] = {a0.x, a0.y, a0.z, a0.w, a1.x, a1.y, a1.z, a1.w};
#pragma unroll
            for (int i = 0; i < 8; i++) {
                acc[i][0] = fmaf(ar[i], w.x, acc[i][0]);
                acc[i][1] = fmaf(ar[i], w.y, acc[i][1]);
                acc[i][2] = fmaf(ar[i], w.z, acc[i][2]);
                acc[i][3] = fmaf(ar[i], w.w, acc[i][3]);
            }
        }
#pragma unroll
        for (int i = 0; i < 8; i++) {
            int n = n0 + i0 + i;
            if (n >= NN) continue;
#pragma unroll
            for (int p = 0; p < 2; p++) {
                int c = c0 + 2 * p;                     // even
                float vA = acc[i][2 * p], vB = acc[i][2 * p + 1];
                if (c < 50) {
                    *(float2*)&outR[(size_t)n * DHID + c] = make_float2(vA, vB);
                } else {
                    int b = (c - 50) / 50, j = (c - 50) - b * 50;  // j even
                    outB[(size_t)n * 125 + b * 25 + (j >> 1)] = __floats2half2_rn(vA, vB);
                }
            }
        }
    }
}

// ---------------- edge pass: one warp per edge, fp16 gather ----------------
template <int L>
__global__ void k_edge(const int* __restrict__ ei, const int* __restrict__ etype,
                       const float* __restrict__ comp, int E) {
    int w = (blockIdx.x * blockDim.x + threadIdx.x) >> 5;
    if (w >= E) return;
    int lane = threadIdx.x & 31;
    int s = __ldg(ei + w);
    int d = __ldg(ei + E + w);
    int t = __ldg(etype + w);
    const float* T      = (L == 1) ? g_T1 : g_T2;
    const __half2* XB   = ((L == 1) ? g_XB1h : g_XB2h) + (size_t)s * 125;
    float* agg          = (L == 1) ? g_agg1 : g_agg2;

    float c0 = __ldg(comp + t * NB + 0);
    float c1 = __ldg(comp + t * NB + 1);
    float c2 = __ldg(comp + t * NB + 2);
    float c3 = __ldg(comp + t * NB + 3);
    float c4 = __ldg(comp + t * NB + 4);

    if (lane < 25) {
        float2 acc = __ldg(((const float2*)(T + t * DHID)) + lane);
        float2 v;
        v = __half22float2(__ldg(XB + lane));       acc.x = fmaf(c0, v.x, acc.x); acc.y = fmaf(c0, v.y, acc.y);
        v = __half22float2(__ldg(XB + 25 + lane));  acc.x = fmaf(c1, v.x, acc.x); acc.y = fmaf(c1, v.y, acc.y);
        v = __half22float2(__ldg(XB + 50 + lane));  acc.x = fmaf(c2, v.x, acc.x); acc.y = fmaf(c2, v.y, acc.y);
        v = __half22float2(__ldg(XB + 75 + lane));  acc.x = fmaf(c3, v.x, acc.x); acc.y = fmaf(c3, v.y, acc.y);
        v = __half22float2(__ldg(XB + 100 + lane)); acc.x = fmaf(c4, v.x, acc.x); acc.y = fmaf(c4, v.y, acc.y);
        atomicAdd(((float2*)(agg + (size_t)d * DHID)) + lane, acc);
    }
    if (L == 1 && lane == 31) atomicAdd(&g_cnt[d], 1.0f);
}

// ---------------- layer-1 epilogue: h = agg/cnt + x@root1 + bias1 ----------------
__global__ void k_node1(const float* __restrict__ bias1) {
    int idx = blockIdx.x * blockDim.x + threadIdx.x;
    if (idx >= NN * DHID) return;
    int n = idx / DHID, j = idx - n * DHID;
    float c = fmaxf(g_cnt[n], 1.0f);
    g_h[idx] = g_agg1[idx] / c + g_rt1[idx] + bias1[j];
}

// ---------------- output: log_softmax over 50 classes, warp per node ----------------
__global__ void k_out(const float* __restrict__ bias2, float* __restrict__ out) {
    int n = (blockIdx.x * blockDim.x + threadIdx.x) >> 5;
    if (n >= NN) return;
    int lane = threadIdx.x & 31;
    float c = fmaxf(g_cnt[n], 1.0f);
    float vx = -1e30f, vy = -1e30f;
    if (lane < 25) {
        float2 a = ((const float2*)g_agg2)[(size_t)n * 25 + lane];
        float2 r = ((const float2*)(g_rt2 + (size_t)n * DHID))[lane];
        vx = a.x / c + r.x + bias2[2 * lane];
        vy = a.y / c + r.y + bias2[2 * lane + 1];
    }
    float m = fmaxf(vx, vy);
#pragma unroll
    for (int o = 16; o > 0; o >>= 1) m = fmaxf(m, __shfl_xor_sync(0xFFFFFFFFu, m, o));
    float sacc = (lane < 25) ? (expf(vx - m) + expf(vy - m)) : 0.f;
#pragma unroll
    for (int o = 16; o > 0; o >>= 1) sacc += __shfl_xor_sync(0xFFFFFFFFu, sacc, o);
    float ls = logf(sacc);
    if (lane < 25)
        ((float2*)out)[(size_t)n * 25 + lane] = make_float2(vx - m - ls, vy - m - ls);
}

// ---------------- launcher ----------------
extern "C" void kernel_launch(void* const* d_in, const int* in_sizes, int n_in,
                              void* d_out, int out_size) {
    const float* x      = (const float*)d_in[0];
    const int*   ei     = (const int*)d_in[1];
    const int*   etype  = (const int*)d_in[2];
    const int*   tgt    = (const int*)d_in[3];
    const float* relE   = (const float*)d_in[4];
    const float* relW   = (const float*)d_in[5];
    const float* basis1 = (const float*)d_in[6];
    const float* comp1  = (const float*)d_in[7];
    const float* root1  = (const float*)d_in[8];
    const float* bias1  = (const float*)d_in[9];
    const float* basis2 = (const float*)d_in[10];
    const float* comp2  = (const float*)d_in[11];
    const float* root2  = (const float*)d_in[12];
    const float* bias2  = (const float*)d_in[13];
    float* out = (float*)d_out;
    int E = in_sizes[1] / 2;

    constexpr int SM1 = (DIN * 300 + DIN * 64) * (int)sizeof(float);   // 145.6 KB
    constexpr int SM2 = (DHID * 300 + DHID * 64) * (int)sizeof(float); //  72.8 KB
    cudaFuncSetAttribute(k_gemm<DIN, 1>, cudaFuncAttributeMaxDynamicSharedMemorySize, SM1);
    cudaFuncSetAttribute(k_gemm<DHID, 2>, cudaFuncAttributeMaxDynamicSharedMemorySize, SM2);

    k_zero<<<4096, 256>>>();
    k_tables<<<NRT, 64>>>(relE, relW, basis1, comp1, basis2, comp2);
    k_gemm<DIN, 1><<<(NN + 63) / 64, 640, SM1>>>(x, basis1, root1, tgt);
    k_edge<1><<<(E + 7) / 8, 256>>>(ei, etype, comp1, E);
    k_node1<<<(NN * DHID + 255) / 256, 256>>>(bias1);
    k_gemm<DHID, 2><<<(NN + 63) / 64, 640, SM2>>>(x /*unused for L2*/, basis2, root2, nullptr);
    k_edge<2><<<(E + 7) / 8, 256>>>(ei, etype, comp2, E);
    k_out<<<(NN + 7) / 8, 256>>>(bias2, out);
}

// round 9
// speedup vs baseline: 1.5340x; 1.2844x over previous
#include <cuda_runtime.h>
#include <cuda_fp16.h>
#include <math.h>
#include <stdint.h>

#define NN 100000        // nodes
#define NE 1600000       // edges (fixed problem shape)
#define DIN 100
#define DHID 50
#define NRT 474          // doubled relation types
#define NB 5             // bases
#define SCAN_CH 512
#define NCH ((NN + SCAN_CH - 1) / SCAN_CH)   // 196
static_assert(NCH <= 256, "scan2 assumes <=256 chunks");

// ---------------- scratch (device globals; no allocation allowed) ----------------
__device__ __half2 g_XB1h[(size_t)NN * 125];   // fp16 gather tables, 50 MB each
__device__ __half2 g_XB2h[(size_t)NN * 125];
__device__ float g_rt1[(size_t)NN * DHID];     // x @ root1 (fp32)
__device__ float g_rt2[(size_t)NN * DHID];     // h @ root2 (fp32)
__device__ float g_h[(size_t)NN * DHID];
__device__ float g_T1[NRT * DHID];
__device__ float g_T2[NRT * DHID];
__device__ float4 g_c4a[NRT]; __device__ float g_c1a[NRT];   // comp1 split
__device__ float4 g_c4b[NRT]; __device__ float g_c1b[NRT];   // comp2 split
// CSR scratch
__device__ int  g_deg[NN];
__device__ int  g_woff[NN];      // exclusive scan; scatter mutates to row END
__device__ int  g_part[256];
__device__ int2 g_st[NE];        // dst-sorted (src, type)

// ---------------- zero degree ----------------
__global__ void k_zero() {
    int i = blockIdx.x * blockDim.x + threadIdx.x;
    if (i < NN) g_deg[i] = 0;
}

// ---------------- histogram over dst ----------------
__global__ void k_hist(const int* __restrict__ ei, int E) {
    int e = blockIdx.x * blockDim.x + threadIdx.x;
    if (e < E) atomicAdd(&g_deg[ei[E + e]], 1);
}

// ---------------- scan phase 1: per-chunk exclusive scan ----------------
__global__ void k_scan1() {
    __shared__ int s[SCAN_CH];
    int t = threadIdx.x, i = blockIdx.x * SCAN_CH + t;
    int v = (i < NN) ? g_deg[i] : 0;
    s[t] = v;
    __syncthreads();
#pragma unroll
    for (int off = 1; off < SCAN_CH; off <<= 1) {
        int x = (t >= off) ? s[t - off] : 0;
        __syncthreads();
        s[t] += x;
        __syncthreads();
    }
    if (i < NN) g_woff[i] = s[t] - v;          // exclusive
    if (t == SCAN_CH - 1) g_part[blockIdx.x] = s[t];
}

// ---------------- scan phase 2: scan chunk totals (1 block) ----------------
__global__ void k_scan2() {
    __shared__ int s[256];
    int t = threadIdx.x;
    int v = (t < NCH) ? g_part[t] : 0;
    s[t] = v;
    __syncthreads();
#pragma unroll
    for (int off = 1; off < 256; off <<= 1) {
        int x = (t >= off) ? s[t - off] : 0;
        __syncthreads();
        s[t] += x;
        __syncthreads();
    }
    if (t < NCH) g_part[t] = s[t] - v;         // exclusive
}

// ---------------- scan phase 3: add chunk base ----------------
__global__ void k_scan3() {
    int i = blockIdx.x * blockDim.x + threadIdx.x;
    if (i < NN) g_woff[i] += g_part[i / SCAN_CH];
}

// ---------------- scatter edges into CSR (ticket order within bin) ----------------
__global__ void k_scatter(const int* __restrict__ ei, const int* __restrict__ etype, int E) {
    int e = blockIdx.x * blockDim.x + threadIdx.x;
    if (e >= E) return;
    int src = ei[e], dst = ei[E + e], t = etype[e];
    int pos = atomicAdd(&g_woff[dst], 1);
    g_st[pos] = make_int2(src, t);
}

// ---------------- per-relation-type tables ----------------
__global__ void k_tables(const float* __restrict__ relE, const float* __restrict__ relW,
                         const float* __restrict__ basis1, const float* __restrict__ comp1,
                         const float* __restrict__ basis2, const float* __restrict__ comp2) {
    int et = blockIdx.x;               // 0..473
    int r = (et < 237) ? et : et - 237;
    __shared__ float sE[DIN];
    __shared__ float sR2[DHID];
    int tid = threadIdx.x;             // 64 threads
    for (int k = tid; k < DIN; k += blockDim.x) sE[k] = relE[r * DIN + k];
    if (tid == 0) {
        g_c4a[et] = make_float4(comp1[et*NB+0], comp1[et*NB+1], comp1[et*NB+2], comp1[et*NB+3]);
        g_c1a[et] = comp1[et*NB+4];
        g_c4b[et] = make_float4(comp2[et*NB+0], comp2[et*NB+1], comp2[et*NB+2], comp2[et*NB+3]);
        g_c1b[et] = comp2[et*NB+4];
    }
    __syncthreads();
    if (tid < DHID) {
        int j = tid;
        float sb[NB] = {0, 0, 0, 0, 0};
        float r2 = 0.f;
        for (int k = 0; k < DIN; k++) {
            float e = sE[k];
#pragma unroll
            for (int b = 0; b < NB; b++)
                sb[b] = fmaf(e, basis1[((size_t)b * DIN + k) * DHID + j], sb[b]);
            r2 = fmaf(e, relW[k * DHID + j], r2);
        }
        float t1 = 0.f;
#pragma unroll
        for (int b = 0; b < NB; b++) t1 = fmaf(comp1[et * NB + b], sb[b], t1);
        g_T1[et * DHID + j] = t1;
        sR2[j] = r2;
    }
    __syncthreads();
    if (tid < DHID) {
        int j = tid;
        float sb[NB] = {0, 0, 0, 0, 0};
        for (int k = 0; k < DHID; k++) {
            float e = sR2[k];
#pragma unroll
            for (int b = 0; b < NB; b++)
                sb[b] = fmaf(e, basis2[((size_t)b * DHID + k) * DHID + j], sb[b]);
        }
        float t2 = 0.f;
#pragma unroll
        for (int b = 0; b < NB; b++) t2 = fmaf(comp2[et * NB + b], sb[b], t2);
        g_T2[et * DHID + j] = t2;
    }
}

// ---------------- node GEMM ----------------
// Output columns: [0..49] = root (fp32), [50..299] = basis (fp16 table).
template <int K, int L>
__global__ void __launch_bounds__(640, 1)
k_gemm(const float* __restrict__ A_in, const float* __restrict__ basisW,
       const float* __restrict__ rootW, const int* __restrict__ targetPtr) {
    extern __shared__ float sm[];
    float* sW = sm;            // [K][300]
    float* sX = sm + K * 300;  // [K][64] (k-major)
    const float* A = (L == 1) ? A_in : g_h;
    __half2* outB = (L == 1) ? g_XB1h : g_XB2h;
    float* outR   = (L == 1) ? g_rt1 : g_rt2;

    int tid = threadIdx.x;
    int n0 = blockIdx.x * 64;
    int target = (L == 1) ? *targetPtr : -1;

    for (int idx = tid; idx < K * 300; idx += 640) {
        int k = idx / 300, c = idx - k * 300;
        float v;
        if (c < 50) {
            v = rootW[k * DHID + c];
        } else {
            int b = (c - 50) / 50, j = (c - 50) - b * 50;
            v = basisW[((size_t)b * K + k) * DHID + j];
        }
        sW[idx] = v;
    }
    for (int idx = tid; idx < K * 64; idx += 640) {
        int i = idx / K, k = idx - i * K;
        int n = n0 + i;
        float v = 0.f;
        if (n < NN && n != target) v = A[(size_t)n * K + k];
        sX[k * 64 + i] = v;
    }
    __syncthreads();

    if (tid < 600) {
        int ng = tid / 75, cg = tid - ng * 75;
        int i0 = ng * 8, c0 = cg * 4;
        float acc[8][4];
#pragma unroll
        for (int i = 0; i < 8; i++)
#pragma unroll
            for (int j = 0; j < 4; j++) acc[i][j] = 0.f;

#pragma unroll 2
        for (int k = 0; k < K; k++) {
            float4 w  = *(const float4*)&sW[k * 300 + c0];
            float4 a0 = *(const float4*)&sX[k * 64 + i0];
            float4 a1 = *(const float4*)&sX[k * 64 + i0 + 4];
            float ar[8] = {a0.x, a0.y, a0.z, a0.w, a1.x, a1.y, a1.z, a1.w};
#pragma unroll
            for (int i = 0; i < 8; i++) {
                acc[i][0] = fmaf(ar[i], w.x, acc[i][0]);
                acc[i][1] = fmaf(ar[i], w.y, acc[i][1]);
                acc[i][2] = fmaf(ar[i], w.z, acc[i][2]);
                acc[i][3] = fmaf(ar[i], w.w, acc[i][3]);
            }
        }
#pragma unroll
        for (int i = 0; i < 8; i++) {
            int n = n0 + i0 + i;
            if (n >= NN) continue;
#pragma unroll
            for (int p = 0; p < 2; p++) {
                int c = c0 + 2 * p;                     // even
                float vA = acc[i][2 * p], vB = acc[i][2 * p + 1];
                if (c < 50) {
                    *(float2*)&outR[(size_t)n * DHID + c] = make_float2(vA, vB);
                } else {
                    int b = (c - 50) / 50, j = (c - 50) - b * 50;  // j even
                    outB[(size_t)n * 125 + b * 25 + (j >> 1)] = __floats2half2_rn(vA, vB);
                }
            }
        }
    }
}

// ---------------- aggregation: warp per node over CSR, atomic-free ----------------
// L==1: writes g_h (device symbol, referenced device-side!) = mean + rt1 + bias1.
// L==2: writes log_softmax(mean + rt2 + bias2) into `out` (harness d_out).
template <int L>
__global__ void k_agg(const float* __restrict__ bias, float* __restrict__ out) {
    int n = (blockIdx.x * blockDim.x + threadIdx.x) >> 5;
    if (n >= NN) return;
    int lane = threadIdx.x & 31;
    int end = g_woff[n];          // row end after scatter
    int d = g_deg[n];
    int start = end - d;
    const float*   T  = (L == 1) ? g_T1  : g_T2;
    const __half2* XB = (L == 1) ? g_XB1h : g_XB2h;
    const float4*  C4 = (L == 1) ? g_c4a : g_c4b;
    const float*   C1 = (L == 1) ? g_c1a : g_c1b;

    float2 acc = make_float2(0.f, 0.f);
    // software-pipelined edge loop: prefetch next (src,type) while gathering current
    int2 st = (start < end) ? __ldg(&g_st[start]) : make_int2(0, 0);
    for (int e = start; e < end; e++) {
        int2 stn = (e + 1 < end) ? __ldg(&g_st[e + 1]) : st;
        if (lane < 25) {
            float4 c  = __ldg(&C4[st.y]);
            float  c4 = __ldg(&C1[st.y]);
            float2 tv = __ldg(((const float2*)(T + st.y * DHID)) + lane);
            const __half2* xr = XB + (size_t)st.x * 125;
            acc.x += tv.x; acc.y += tv.y;
            float2 v;
            v = __half22float2(__ldg(xr + lane));       acc.x = fmaf(c.x, v.x, acc.x); acc.y = fmaf(c.x, v.y, acc.y);
            v = __half22float2(__ldg(xr + 25 + lane));  acc.x = fmaf(c.y, v.x, acc.x); acc.y = fmaf(c.y, v.y, acc.y);
            v = __half22float2(__ldg(xr + 50 + lane));  acc.x = fmaf(c.z, v.x, acc.x); acc.y = fmaf(c.z, v.y, acc.y);
            v = __half22float2(__ldg(xr + 75 + lane));  acc.x = fmaf(c.w, v.x, acc.x); acc.y = fmaf(c.w, v.y, acc.y);
            v = __half22float2(__ldg(xr + 100 + lane)); acc.x = fmaf(c4,  v.x, acc.x); acc.y = fmaf(c4,  v.y, acc.y);
        }
        st = stn;
    }
    float cn = fmaxf((float)d, 1.0f);
    if (L == 1) {
        if (lane < 25) {
            float2 r  = __ldg(((const float2*)(g_rt1 + (size_t)n * DHID)) + lane);
            float2 bb = __ldg(((const float2*)bias) + lane);
            ((float2*)(g_h + (size_t)n * DHID))[lane] =
                make_float2(acc.x / cn + r.x + bb.x, acc.y / cn + r.y + bb.y);
        }
    } else {
        float vx = -1e30f, vy = -1e30f;
        if (lane < 25) {
            float2 r  = __ldg(((const float2*)(g_rt2 + (size_t)n * DHID)) + lane);
            float2 bb = __ldg(((const float2*)bias) + lane);
            vx = acc.x / cn + r.x + bb.x;
            vy = acc.y / cn + r.y + bb.y;
        }
        float m = fmaxf(vx, vy);
#pragma unroll
        for (int o = 16; o > 0; o >>= 1) m = fmaxf(m, __shfl_xor_sync(0xFFFFFFFFu, m, o));
        float sacc = (lane < 25) ? (expf(vx - m) + expf(vy - m)) : 0.f;
#pragma unroll
        for (int o = 16; o > 0; o >>= 1) sacc += __shfl_xor_sync(0xFFFFFFFFu, sacc, o);
        float ls = logf(sacc);
        if (lane < 25)
            ((float2*)(out + (size_t)n * DHID))[lane] = make_float2(vx - m - ls, vy - m - ls);
    }
}

// ---------------- launcher ----------------
extern "C" void kernel_launch(void* const* d_in, const int* in_sizes, int n_in,
                              void* d_out, int out_size) {
    const float* x      = (const float*)d_in[0];
    const int*   ei     = (const int*)d_in[1];
    const int*   etype  = (const int*)d_in[2];
    const int*   tgt    = (const int*)d_in[3];
    const float* relE   = (const float*)d_in[4];
    const float* relW   = (const float*)d_in[5];
    const float* basis1 = (const float*)d_in[6];
    const float* comp1  = (const float*)d_in[7];
    const float* root1  = (const float*)d_in[8];
    const float* bias1  = (const float*)d_in[9];
    const float* basis2 = (const float*)d_in[10];
    const float* comp2  = (const float*)d_in[11];
    const float* root2  = (const float*)d_in[12];
    const float* bias2  = (const float*)d_in[13];
    float* out = (float*)d_out;
    int E = in_sizes[1] / 2;

    constexpr int SM1 = (DIN * 300 + DIN * 64) * (int)sizeof(float);   // 145.6 KB
    constexpr int SM2 = (DHID * 300 + DHID * 64) * (int)sizeof(float); //  72.8 KB
    cudaFuncSetAttribute(k_gemm<DIN, 1>, cudaFuncAttributeMaxDynamicSharedMemorySize, SM1);
    cudaFuncSetAttribute(k_gemm<DHID, 2>, cudaFuncAttributeMaxDynamicSharedMemorySize, SM2);

    // CSR build (reused by both layers)
    k_zero<<<(NN + 255) / 256, 256>>>();
    k_tables<<<NRT, 64>>>(relE, relW, basis1, comp1, basis2, comp2);
    k_hist<<<(E + 255) / 256, 256>>>(ei, E);
    k_scan1<<<NCH, SCAN_CH>>>();
    k_scan2<<<1, 256>>>();
    k_scan3<<<(NN + 255) / 256, 256>>>();
    k_scatter<<<(E + 255) / 256, 256>>>(ei, etype, E);

    // layer 1  (k_agg<1> writes g_h via the device-side symbol; out param unused)
    k_gemm<DIN, 1><<<(NN + 63) / 64, 640, SM1>>>(x, basis1, root1, tgt);
    k_agg<1><<<(NN + 7) / 8, 256>>>(bias1, nullptr);
    // layer 2
    k_gemm<DHID, 2><<<(NN + 63) / 64, 640, SM2>>>(x /*unused*/, basis2, root2, nullptr);
    k_agg<2><<<(NN + 7) / 8, 256>>>(bias2, out);
}

// round 10
// speedup vs baseline: 1.6788x; 1.0944x over previous
#include <cuda_runtime.h>
#include <cuda_fp16.h>
#include <math.h>
#include <stdint.h>

#define NN 100000        // nodes
#define NE 1600000       // edges (fixed problem shape)
#define DIN 100
#define DHID 50
#define NRT 474          // doubled relation types
#define NB 5             // bases
#define SCAN_CH 512
#define NCH ((NN + SCAN_CH - 1) / SCAN_CH)   // 196
#define NTILE ((NN + 63) / 64)               // 1563 node tiles of 64
static_assert(NCH <= 256, "scan2 assumes <=256 chunks");

// ---------------- scratch (device globals; no allocation allowed) ----------------
__device__ __half2 g_XB1h[(size_t)NN * 125];   // fp16 gather tables, 50 MB each
__device__ __half2 g_XB2h[(size_t)NN * 125];
__device__ float g_rt1[(size_t)NN * DHID];     // x @ root1 (fp32)
__device__ float g_rt2[(size_t)NN * DHID];     // h @ root2 (fp32)
__device__ float g_h[(size_t)NN * DHID];
__device__ float g_T1[NRT * DHID];
__device__ float g_T2[NRT * DHID];
__device__ float4 g_c4a[NRT]; __device__ float g_c1a[NRT];   // comp1 split
__device__ float4 g_c4b[NRT]; __device__ float g_c1b[NRT];   // comp2 split
// CSR scratch
__device__ int  g_deg[NN];
__device__ int  g_woff[NN];      // exclusive scan; scatter mutates to row END
__device__ int  g_part[256];
__device__ int2 g_st[NE];        // dst-sorted (src, type)

// ---------------- zero degree ----------------
__global__ void k_zero() {
    int i = blockIdx.x * blockDim.x + threadIdx.x;
    if (i < NN) g_deg[i] = 0;
}

// ---------------- histogram over dst ----------------
__global__ void k_hist(const int* __restrict__ ei, int E) {
    int e = blockIdx.x * blockDim.x + threadIdx.x;
    if (e < E) atomicAdd(&g_deg[ei[E + e]], 1);
}

// ---------------- scan phase 1: per-chunk exclusive scan ----------------
__global__ void k_scan1() {
    __shared__ int s[SCAN_CH];
    int t = threadIdx.x, i = blockIdx.x * SCAN_CH + t;
    int v = (i < NN) ? g_deg[i] : 0;
    s[t] = v;
    __syncthreads();
#pragma unroll
    for (int off = 1; off < SCAN_CH; off <<= 1) {
        int x = (t >= off) ? s[t - off] : 0;
        __syncthreads();
        s[t] += x;
        __syncthreads();
    }
    if (i < NN) g_woff[i] = s[t] - v;          // exclusive
    if (t == SCAN_CH - 1) g_part[blockIdx.x] = s[t];
}

// ---------------- scan phase 2: scan chunk totals (1 block) ----------------
__global__ void k_scan2() {
    __shared__ int s[256];
    int t = threadIdx.x;
    int v = (t < NCH) ? g_part[t] : 0;
    s[t] = v;
    __syncthreads();
#pragma unroll
    for (int off = 1; off < 256; off <<= 1) {
        int x = (t >= off) ? s[t - off] : 0;
        __syncthreads();
        s[t] += x;
        __syncthreads();
    }
    if (t < NCH) g_part[t] = s[t] - v;         // exclusive
}

// ---------------- scan phase 3: add chunk base ----------------
__global__ void k_scan3() {
    int i = blockIdx.x * blockDim.x + threadIdx.x;
    if (i < NN) g_woff[i] += g_part[i / SCAN_CH];
}

// ---------------- scatter edges into CSR (ticket order within bin) ----------------
__global__ void k_scatter(const int* __restrict__ ei, const int* __restrict__ etype, int E) {
    int e = blockIdx.x * blockDim.x + threadIdx.x;
    if (e >= E) return;
    int src = ei[e], dst = ei[E + e], t = etype[e];
    int pos = atomicAdd(&g_woff[dst], 1);
    g_st[pos] = make_int2(src, t);
}

// ---------------- per-relation-type tables ----------------
__global__ void k_tables(const float* __restrict__ relE, const float* __restrict__ relW,
                         const float* __restrict__ basis1, const float* __restrict__ comp1,
                         const float* __restrict__ basis2, const float* __restrict__ comp2) {
    int et = blockIdx.x;               // 0..473
    int r = (et < 237) ? et : et - 237;
    __shared__ float sE[DIN];
    __shared__ float sR2[DHID];
    int tid = threadIdx.x;             // 64 threads
    for (int k = tid; k < DIN; k += blockDim.x) sE[k] = relE[r * DIN + k];
    if (tid == 0) {
        g_c4a[et] = make_float4(comp1[et*NB+0], comp1[et*NB+1], comp1[et*NB+2], comp1[et*NB+3]);
        g_c1a[et] = comp1[et*NB+4];
        g_c4b[et] = make_float4(comp2[et*NB+0], comp2[et*NB+1], comp2[et*NB+2], comp2[et*NB+3]);
        g_c1b[et] = comp2[et*NB+4];
    }
    __syncthreads();
    if (tid < DHID) {
        int j = tid;
        float sb[NB] = {0, 0, 0, 0, 0};
        float r2 = 0.f;
        for (int k = 0; k < DIN; k++) {
            float e = sE[k];
#pragma unroll
            for (int b = 0; b < NB; b++)
                sb[b] = fmaf(e, basis1[((size_t)b * DIN + k) * DHID + j], sb[b]);
            r2 = fmaf(e, relW[k * DHID + j], r2);
        }
        float t1 = 0.f;
#pragma unroll
        for (int b = 0; b < NB; b++) t1 = fmaf(comp1[et * NB + b], sb[b], t1);
        g_T1[et * DHID + j] = t1;
        sR2[j] = r2;
    }
    __syncthreads();
    if (tid < DHID) {
        int j = tid;
        float sb[NB] = {0, 0, 0, 0, 0};
        for (int k = 0; k < DHID; k++) {
            float e = sR2[k];
#pragma unroll
            for (int b = 0; b < NB; b++)
                sb[b] = fmaf(e, basis2[((size_t)b * DHID + k) * DHID + j], sb[b]);
        }
        float t2 = 0.f;
#pragma unroll
        for (int b = 0; b < NB; b++) t2 = fmaf(comp2[et * NB + b], sb[b], t2);
        g_T2[et * DHID + j] = t2;
    }
}

// ---------------- persistent node GEMM ----------------
// W (K x 300) loaded into smem ONCE per block; block loops over node tiles with
// register-staged double buffering of the X tile.
// Output columns: [0..49] = root (fp32), [50..299] = basis (fp16 table).
template <int K, int L>
__global__ void __launch_bounds__(640, 1)
k_gemm(const float* __restrict__ A_in, const float* __restrict__ basisW,
       const float* __restrict__ rootW, const int* __restrict__ targetPtr) {
    extern __shared__ float sm[];
    float* sW = sm;            // [K][300]
    float* sX = sm + K * 300;  // [K][64] (k-major)
    const float* A = (L == 1) ? A_in : g_h;
    __half2* outB = (L == 1) ? g_XB1h : g_XB2h;
    float* outR   = (L == 1) ? g_rt1 : g_rt2;
    constexpr int SREG = K * 64 / 640;   // 10 (K=100) / 5 (K=50)

    int tid = threadIdx.x;
    int target = (L == 1) ? *targetPtr : -1;

    // load W once
    for (int idx = tid; idx < K * 300; idx += 640) {
        int k = idx / 300, c = idx - k * 300;
        float v;
        if (c < 50) {
            v = rootW[k * DHID + c];
        } else {
            int b = (c - 50) / 50, j = (c - 50) - b * 50;
            v = basisW[((size_t)b * K + k) * DHID + j];
        }
        sW[idx] = v;
    }

    // preload first tile into smem
    int t0 = blockIdx.x;
    {
        int n0 = t0 * 64;
#pragma unroll
        for (int j = 0; j < SREG; j++) {
            int idx = tid + j * 640;
            int i = idx / K, k = idx - i * K;
            int n = n0 + i;
            float v = 0.f;
            if (n < NN && n != target) v = A[(size_t)n * K + k];
            sX[k * 64 + i] = v;
        }
    }
    __syncthreads();

    int ng = tid / 75, cg = tid - ng * 75;     // valid for tid<600
    int i0 = ng * 8, c0 = cg * 4;

    for (int t = t0; t < NTILE; t += gridDim.x) {
        int tn = t + gridDim.x;
        // stage next tile into registers (overlaps with compute below)
        float stage[SREG];
        if (tn < NTILE) {
            int n0n = tn * 64;
#pragma unroll
            for (int j = 0; j < SREG; j++) {
                int idx = tid + j * 640;
                int i = idx / K, k = idx - i * K;
                int n = n0n + i;
                float v = 0.f;
                if (n < NN && n != target) v = A[(size_t)n * K + k];
                stage[j] = v;
            }
        }

        if (tid < 600) {
            float acc[8][4];
#pragma unroll
            for (int i = 0; i < 8; i++)
#pragma unroll
                for (int j = 0; j < 4; j++) acc[i][j] = 0.f;

#pragma unroll 2
            for (int k = 0; k < K; k++) {
                float4 w  = *(const float4*)&sW[k * 300 + c0];
                float4 a0 = *(const float4*)&sX[k * 64 + i0];
                float4 a1 = *(const float4*)&sX[k * 64 + i0 + 4];
                float ar[8] = {a0.x, a0.y, a0.z, a0.w, a1.x, a1.y, a1.z, a1.w};
#pragma unroll
                for (int i = 0; i < 8; i++) {
                    acc[i][0] = fmaf(ar[i], w.x, acc[i][0]);
                    acc[i][1] = fmaf(ar[i], w.y, acc[i][1]);
                    acc[i][2] = fmaf(ar[i], w.z, acc[i][2]);
                    acc[i][3] = fmaf(ar[i], w.w, acc[i][3]);
                }
            }
            int n0 = t * 64;
#pragma unroll
            for (int i = 0; i < 8; i++) {
                int n = n0 + i0 + i;
                if (n >= NN) continue;
#pragma unroll
                for (int p = 0; p < 2; p++) {
                    int c = c0 + 2 * p;                     // even
                    float vA = acc[i][2 * p], vB = acc[i][2 * p + 1];
                    if (c < 50) {
                        *(float2*)&outR[(size_t)n * DHID + c] = make_float2(vA, vB);
                    } else {
                        int b = (c - 50) / 50, j = (c - 50) - b * 50;  // j even
                        outB[(size_t)n * 125 + b * 25 + (j >> 1)] = __floats2half2_rn(vA, vB);
                    }
                }
            }
        }
        __syncthreads();                 // compute done before sX overwrite
        if (tn < NTILE) {
#pragma unroll
            for (int j = 0; j < SREG; j++) {
                int idx = tid + j * 640;
                int i = idx / K, k = idx - i * K;
                sX[k * 64 + i] = stage[j];
            }
        }
        __syncthreads();                 // sX ready for next iter
    }
}

// ---------------- aggregation: warp per node over CSR, atomic-free, 2-edge unroll --
// L==1: writes g_h (device-side symbol) = mean + rt1 + bias1.
// L==2: writes log_softmax(mean + rt2 + bias2) into `out` (harness d_out).
template <int L>
__global__ void k_agg(const float* __restrict__ bias, float* __restrict__ out) {
    int n = (blockIdx.x * blockDim.x + threadIdx.x) >> 5;
    if (n >= NN) return;
    int lane = threadIdx.x & 31;
    int end = g_woff[n];          // row end after scatter
    int d = g_deg[n];
    int start = end - d;
    const float*   T  = (L == 1) ? g_T1  : g_T2;
    const __half2* XB = (L == 1) ? g_XB1h : g_XB2h;
    const float4*  C4 = (L == 1) ? g_c4a : g_c4b;
    const float*   C1 = (L == 1) ? g_c1a : g_c1b;

    float2 acc  = make_float2(0.f, 0.f);
    float2 acc2 = make_float2(0.f, 0.f);
    int e = start;
    for (; e + 1 < end; e += 2) {
        int2 s0 = __ldg(&g_st[e]);
        int2 s1 = __ldg(&g_st[e + 1]);
        if (lane < 25) {
            float4 ca = __ldg(&C4[s0.y]); float c4a = __ldg(&C1[s0.y]);
            float4 cb = __ldg(&C4[s1.y]); float c4b = __ldg(&C1[s1.y]);
            float2 t0 = __ldg(((const float2*)(T + s0.y * DHID)) + lane);
            float2 t1 = __ldg(((const float2*)(T + s1.y * DHID)) + lane);
            const __half2* x0 = XB + (size_t)s0.x * 125;
            const __half2* x1 = XB + (size_t)s1.x * 125;
            acc.x  += t0.x; acc.y  += t0.y;
            acc2.x += t1.x; acc2.y += t1.y;
            float2 v;
            v = __half22float2(__ldg(x0 + lane));       acc.x  = fmaf(ca.x, v.x, acc.x);  acc.y  = fmaf(ca.x, v.y, acc.y);
            v = __half22float2(__ldg(x1 + lane));       acc2.x = fmaf(cb.x, v.x, acc2.x); acc2.y = fmaf(cb.x, v.y, acc2.y);
            v = __half22float2(__ldg(x0 + 25 + lane));  acc.x  = fmaf(ca.y, v.x, acc.x);  acc.y  = fmaf(ca.y, v.y, acc.y);
            v = __half22float2(__ldg(x1 + 25 + lane));  acc2.x = fmaf(cb.y, v.x, acc2.x); acc2.y = fmaf(cb.y, v.y, acc2.y);
            v = __half22float2(__ldg(x0 + 50 + lane));  acc.x  = fmaf(ca.z, v.x, acc.x);  acc.y  = fmaf(ca.z, v.y, acc.y);
            v = __half22float2(__ldg(x1 + 50 + lane));  acc2.x = fmaf(cb.z, v.x, acc2.x); acc2.y = fmaf(cb.z, v.y, acc2.y);
            v = __half22float2(__ldg(x0 + 75 + lane));  acc.x  = fmaf(ca.w, v.x, acc.x);  acc.y  = fmaf(ca.w, v.y, acc.y);
            v = __half22float2(__ldg(x1 + 75 + lane));  acc2.x = fmaf(cb.w, v.x, acc2.x); acc2.y = fmaf(cb.w, v.y, acc2.y);
            v = __half22float2(__ldg(x0 + 100 + lane)); acc.x  = fmaf(c4a,  v.x, acc.x);  acc.y  = fmaf(c4a,  v.y, acc.y);
            v = __half22float2(__ldg(x1 + 100 + lane)); acc2.x = fmaf(c4b,  v.x, acc2.x); acc2.y = fmaf(c4b,  v.y, acc2.y);
        }
    }
    if (e < end) {
        int2 s0 = __ldg(&g_st[e]);
        if (lane < 25) {
            float4 ca = __ldg(&C4[s0.y]); float c4a = __ldg(&C1[s0.y]);
            float2 t0 = __ldg(((const float2*)(T + s0.y * DHID)) + lane);
            const __half2* x0 = XB + (size_t)s0.x * 125;
            acc.x += t0.x; acc.y += t0.y;
            float2 v;
            v = __half22float2(__ldg(x0 + lane));       acc.x = fmaf(ca.x, v.x, acc.x); acc.y = fmaf(ca.x, v.y, acc.y);
            v = __half22float2(__ldg(x0 + 25 + lane));  acc.x = fmaf(ca.y, v.x, acc.x); acc.y = fmaf(ca.y, v.y, acc.y);
            v = __half22float2(__ldg(x0 + 50 + lane));  acc.x = fmaf(ca.z, v.x, acc.x); acc.y = fmaf(ca.z, v.y, acc.y);
            v = __half22float2(__ldg(x0 + 75 + lane));  acc.x = fmaf(ca.w, v.x, acc.x); acc.y = fmaf(ca.w, v.y, acc.y);
            v = __half22float2(__ldg(x0 + 100 + lane)); acc.x = fmaf(c4a,  v.x, acc.x); acc.y = fmaf(c4a,  v.y, acc.y);
        }
    }
    acc.x += acc2.x; acc.y += acc2.y;

    float cn = fmaxf((float)d, 1.0f);
    if (L == 1) {
        if (lane < 25) {
            float2 r  = __ldg(((const float2*)(g_rt1 + (size_t)n * DHID)) + lane);
            float2 bb = __ldg(((const float2*)bias) + lane);
            ((float2*)(g_h + (size_t)n * DHID))[lane] =
                make_float2(acc.x / cn + r.x + bb.x, acc.y / cn + r.y + bb.y);
        }
    } else {
        float vx = -1e30f, vy = -1e30f;
        if (lane < 25) {
            float2 r  = __ldg(((const float2*)(g_rt2 + (size_t)n * DHID)) + lane);
            float2 bb = __ldg(((const float2*)bias) + lane);
            vx = acc.x / cn + r.x + bb.x;
            vy = acc.y / cn + r.y + bb.y;
        }
        float m = fmaxf(vx, vy);
#pragma unroll
        for (int o = 16; o > 0; o >>= 1) m = fmaxf(m, __shfl_xor_sync(0xFFFFFFFFu, m, o));
        float sacc = (lane < 25) ? (expf(vx - m) + expf(vy - m)) : 0.f;
#pragma unroll
        for (int o = 16; o > 0; o >>= 1) sacc += __shfl_xor_sync(0xFFFFFFFFu, sacc, o);
        float ls = logf(sacc);
        if (lane < 25)
            ((float2*)(out + (size_t)n * DHID))[lane] = make_float2(vx - m - ls, vy - m - ls);
    }
}

// ---------------- launcher ----------------
extern "C" void kernel_launch(void* const* d_in, const int* in_sizes, int n_in,
                              void* d_out, int out_size) {
    const float* x      = (const float*)d_in[0];
    const int*   ei     = (const int*)d_in[1];
    const int*   etype  = (const int*)d_in[2];
    const int*   tgt    = (const int*)d_in[3];
    const float* relE   = (const float*)d_in[4];
    const float* relW   = (const float*)d_in[5];
    const float* basis1 = (const float*)d_in[6];
    const float* comp1  = (const float*)d_in[7];
    const float* root1  = (const float*)d_in[8];
    const float* bias1  = (const float*)d_in[9];
    const float* basis2 = (const float*)d_in[10];
    const float* comp2  = (const float*)d_in[11];
    const float* root2  = (const float*)d_in[12];
    const float* bias2  = (const float*)d_in[13];
    float* out = (float*)d_out;
    int E = in_sizes[1] / 2;

    constexpr int SM1 = (DIN * 300 + DIN * 64) * (int)sizeof(float);   // 145.6 KB
    constexpr int SM2 = (DHID * 300 + DHID * 64) * (int)sizeof(float); //  72.8 KB
    cudaFuncSetAttribute(k_gemm<DIN, 1>, cudaFuncAttributeMaxDynamicSharedMemorySize, SM1);
    cudaFuncSetAttribute(k_gemm<DHID, 2>, cudaFuncAttributeMaxDynamicSharedMemorySize, SM2);

    // CSR build (reused by both layers)
    k_zero<<<(NN + 255) / 256, 256>>>();
    k_tables<<<NRT, 64>>>(relE, relW, basis1, comp1, basis2, comp2);
    k_hist<<<(E + 255) / 256, 256>>>(ei, E);
    k_scan1<<<NCH, SCAN_CH>>>();
    k_scan2<<<1, 256>>>();
    k_scan3<<<(NN + 255) / 256, 256>>>();
    k_scatter<<<(E + 255) / 256, 256>>>(ei, etype, E);

    // layer 1 (persistent GEMM: W staged once per block)
    k_gemm<DIN, 1><<<148, 640, SM1>>>(x, basis1, root1, tgt);
    k_agg<1><<<(NN + 7) / 8, 256>>>(bias1, nullptr);
    // layer 2 (2 blocks/SM fit at 72.8 KB smem)
    k_gemm<DHID, 2><<<296, 640, SM2>>>(x /*unused*/, basis2, root2, nullptr);
    k_agg<2><<<(NN + 7) / 8, 256>>>(bias2, out);
}

// round 11
// speedup vs baseline: 1.8510x; 1.1026x over previous
#include <cuda_runtime.h>
#include <cuda_fp16.h>
#include <math.h>
#include <stdint.h>

#define NN 100000        // nodes
#define NE 1600000       // edges (fixed problem shape)
#define DIN 100
#define DHID 50
#define NRT 474          // doubled relation types
#define NB 5             // bases
#define SCAN_CH 512
#define NCH ((NN + SCAN_CH - 1) / SCAN_CH)   // 196
#define NT128 ((NN + 127) / 128)             // 782 node tiles of 128
#define NW 312                               // padded W smem row stride (words)
static_assert(NCH <= 256, "scan2 assumes <=256 chunks");

// ---------------- scratch (device globals; no allocation allowed) ----------------
__device__ __half2 g_XB1h[(size_t)NN * 125];   // fp16 gather tables, 50 MB each
__device__ __half2 g_XB2h[(size_t)NN * 125];
__device__ float g_rt1[(size_t)NN * DHID];     // x @ root1 (fp32)
__device__ float g_rt2[(size_t)NN * DHID];     // h @ root2 (fp32)
__device__ float g_h[(size_t)NN * DHID];
__device__ float g_T1[NRT * DHID];
__device__ float g_T2[NRT * DHID];
__device__ float4 g_c4a[NRT]; __device__ float g_c1a[NRT];   // comp1 split
__device__ float4 g_c4b[NRT]; __device__ float g_c1b[NRT];   // comp2 split
// CSR scratch
__device__ int  g_deg[NN];
__device__ int  g_woff[NN];      // exclusive scan; scatter mutates to row END
__device__ int  g_part[256];
__device__ int2 g_st[NE];        // dst-sorted (src, type)

// ---------------- zero degree ----------------
__global__ void k_zero() {
    int i = blockIdx.x * blockDim.x + threadIdx.x;
    if (i < NN) g_deg[i] = 0;
}

// ---------------- histogram over dst ----------------
__global__ void k_hist(const int* __restrict__ ei, int E) {
    int e = blockIdx.x * blockDim.x + threadIdx.x;
    if (e < E) atomicAdd(&g_deg[ei[E + e]], 1);
}

// ---------------- scan phase 1: per-chunk exclusive scan ----------------
__global__ void k_scan1() {
    __shared__ int s[SCAN_CH];
    int t = threadIdx.x, i = blockIdx.x * SCAN_CH + t;
    int v = (i < NN) ? g_deg[i] : 0;
    s[t] = v;
    __syncthreads();
#pragma unroll
    for (int off = 1; off < SCAN_CH; off <<= 1) {
        int x = (t >= off) ? s[t - off] : 0;
        __syncthreads();
        s[t] += x;
        __syncthreads();
    }
    if (i < NN) g_woff[i] = s[t] - v;          // exclusive
    if (t == SCAN_CH - 1) g_part[blockIdx.x] = s[t];
}

// ---------------- scan phase 2: scan chunk totals (1 block) ----------------
__global__ void k_scan2() {
    __shared__ int s[256];
    int t = threadIdx.x;
    int v = (t < NCH) ? g_part[t] : 0;
    s[t] = v;
    __syncthreads();
#pragma unroll
    for (int off = 1; off < 256; off <<= 1) {
        int x = (t >= off) ? s[t - off] : 0;
        __syncthreads();
        s[t] += x;
        __syncthreads();
    }
    if (t < NCH) g_part[t] = s[t] - v;         // exclusive
}

// ---------------- scan phase 3: add chunk base ----------------
__global__ void k_scan3() {
    int i = blockIdx.x * blockDim.x + threadIdx.x;
    if (i < NN) g_woff[i] += g_part[i / SCAN_CH];
}

// ---------------- scatter edges into CSR (ticket order within bin) ----------------
__global__ void k_scatter(const int* __restrict__ ei, const int* __restrict__ etype, int E) {
    int e = blockIdx.x * blockDim.x + threadIdx.x;
    if (e >= E) return;
    int src = ei[e], dst = ei[E + e], t = etype[e];
    int pos = atomicAdd(&g_woff[dst], 1);
    g_st[pos] = make_int2(src, t);
}

// ---------------- per-relation-type tables ----------------
__global__ void k_tables(const float* __restrict__ relE, const float* __restrict__ relW,
                         const float* __restrict__ basis1, const float* __restrict__ comp1,
                         const float* __restrict__ basis2, const float* __restrict__ comp2) {
    int et = blockIdx.x;               // 0..473
    int r = (et < 237) ? et : et - 237;
    __shared__ float sE[DIN];
    __shared__ float sR2[DHID];
    int tid = threadIdx.x;             // 64 threads
    for (int k = tid; k < DIN; k += blockDim.x) sE[k] = relE[r * DIN + k];
    if (tid == 0) {
        g_c4a[et] = make_float4(comp1[et*NB+0], comp1[et*NB+1], comp1[et*NB+2], comp1[et*NB+3]);
        g_c1a[et] = comp1[et*NB+4];
        g_c4b[et] = make_float4(comp2[et*NB+0], comp2[et*NB+1], comp2[et*NB+2], comp2[et*NB+3]);
        g_c1b[et] = comp2[et*NB+4];
    }
    __syncthreads();
    if (tid < DHID) {
        int j = tid;
        float sb[NB] = {0, 0, 0, 0, 0};
        float r2 = 0.f;
        for (int k = 0; k < DIN; k++) {
            float e = sE[k];
#pragma unroll
            for (int b = 0; b < NB; b++)
                sb[b] = fmaf(e, basis1[((size_t)b * DIN + k) * DHID + j], sb[b]);
            r2 = fmaf(e, relW[k * DHID + j], r2);
        }
        float t1 = 0.f;
#pragma unroll
        for (int b = 0; b < NB; b++) t1 = fmaf(comp1[et * NB + b], sb[b], t1);
        g_T1[et * DHID + j] = t1;
        sR2[j] = r2;
    }
    __syncthreads();
    if (tid < DHID) {
        int j = tid;
        float sb[NB] = {0, 0, 0, 0, 0};
        for (int k = 0; k < DHID; k++) {
            float e = sR2[k];
#pragma unroll
            for (int b = 0; b < NB; b++)
                sb[b] = fmaf(e, basis2[((size_t)b * DHID + k) * DHID + j], sb[b]);
        }
        float t2 = 0.f;
#pragma unroll
        for (int b = 0; b < NB; b++) t2 = fmaf(comp2[et * NB + b], sb[b], t2);
        g_T2[et * DHID + j] = t2;
    }
}

// ---------------- tf32 helpers ----------------
__device__ __forceinline__ uint32_t f2tf32(float v) {
    uint32_t t;
    asm("cvt.rna.tf32.f32 %0, %1;" : "=r"(t) : "f"(v));
    return t;
}
__device__ __forceinline__ void mma_tf32(float c[4], const uint32_t a[4],
                                         uint32_t b0, uint32_t b1) {
    asm volatile(
        "mma.sync.aligned.m16n8k8.row.col.f32.tf32.tf32.f32 "
        "{%0,%1,%2,%3}, {%4,%5,%6,%7}, {%8,%9}, {%0,%1,%2,%3};"
        : "+f"(c[0]), "+f"(c[1]), "+f"(c[2]), "+f"(c[3])
        : "r"(a[0]), "r"(a[1]), "r"(a[2]), "r"(a[3]), "r"(b0), "r"(b1));
}

// pairwise store into the split output (col even)
template <int L>
__device__ __forceinline__ void store_pair(int n, int col, float vA, float vB) {
    float*   outR = (L == 1) ? g_rt1 : g_rt2;
    __half2* outB = (L == 1) ? g_XB1h : g_XB2h;
    if (col < 50) {
        *(float2*)&outR[(size_t)n * DHID + col] = make_float2(vA, vB);
    } else {
        int b = (col - 50) / 50, j = (col - 50) - b * 50;   // j even
        outB[(size_t)n * 125 + b * 25 + (j >> 1)] = __floats2half2_rn(vA, vB);
    }
}

// ---------------- tensor-core node GEMM (tf32 mma.sync) ----------------
// Persistent: W staged once (tf32 bits in smem, row stride NW=312 -> conflict-free),
// loop over 128-node tiles. 8 warps, warp w owns rows [w*16, w*16+16).
// A fragments register-resident across all 38 n-tiles; n-tiles processed in pairs.
template <int K, int L>
__global__ void __launch_bounds__(256, (L == 1) ? 1 : 2)
k_gemm_t(const float* __restrict__ A_in, const float* __restrict__ basisW,
         const float* __restrict__ rootW, const int* __restrict__ targetPtr) {
    constexpr int KT = (K + 7) / 8;      // 13 / 7 k-tiles
    constexpr int KP = KT * 8;           // 104 / 56
    constexpr int KS = KP + 4;           // padded A row stride: 108 / 60 (bank-clean)
    extern __shared__ uint32_t smu[];
    uint32_t* sW = smu;                  // [KP][NW]
    uint32_t* sA = smu + KP * NW;        // [128][KS]
    const float* A = (L == 1) ? A_in : g_h;

    int tid = threadIdx.x;
    int target = (L == 1) ? *targetPtr : -1;

    // stage W once (tf32 bits; zero padding)
    for (int idx = tid; idx < KP * NW; idx += 256) {
        int k = idx / NW, c = idx - k * NW;
        float v = 0.f;
        if (k < K && c < 300) {
            if (c < 50) v = rootW[k * DHID + c];
            else { int b = (c - 50) / 50, j = (c - 50) - b * 50;
                   v = basisW[((size_t)b * K + k) * DHID + j]; }
        }
        sW[idx] = f2tf32(v);
    }

    int lane = tid & 31, warp = tid >> 5;
    int gid = lane >> 2, tig = lane & 3;
    int wr = warp * 16;

    for (int t = blockIdx.x; t < NT128; t += gridDim.x) {
        int n0 = t * 128;
        __syncthreads();   // prev-iter compute done (also covers W staging, iter 0)
        for (int idx = tid; idx < 128 * KS; idx += 256) {
            int i = idx / KS, k = idx - i * KS;
            int n = n0 + i;
            float v = 0.f;
            if (k < K && n < NN && n != target) v = A[(size_t)n * K + k];
            sA[idx] = f2tf32(v);
        }
        __syncthreads();

        // A fragments for this warp's 16 rows, all k-tiles
        uint32_t aF[KT][4];
#pragma unroll
        for (int kt = 0; kt < KT; kt++) {
            int r0 = (wr + gid) * KS, r1 = (wr + gid + 8) * KS;
            int kk = kt * 8 + tig;
            aF[kt][0] = sA[r0 + kk];
            aF[kt][1] = sA[r1 + kk];
            aF[kt][2] = sA[r0 + kk + 4];
            aF[kt][3] = sA[r1 + kk + 4];
        }

        int nrow0 = n0 + wr + gid;
        int nrow1 = nrow0 + 8;
        for (int nt = 0; nt < 38; nt += 2) {
            float c0[4] = {0.f, 0.f, 0.f, 0.f};
            float c1[4] = {0.f, 0.f, 0.f, 0.f};
            int nb = nt * 8 + gid;
#pragma unroll
            for (int kt = 0; kt < KT; kt++) {
                int kb = kt * 8 + tig;
                uint32_t b0a = sW[kb * NW + nb];
                uint32_t b1a = sW[(kb + 4) * NW + nb];
                uint32_t b0b = sW[kb * NW + nb + 8];
                uint32_t b1b = sW[(kb + 4) * NW + nb + 8];
                mma_tf32(c0, aF[kt], b0a, b1a);
                mma_tf32(c1, aF[kt], b0b, b1b);
            }
            int colA = nt * 8 + tig * 2;       // even
            int colB = colA + 8;
            if (nrow0 < NN) {
                store_pair<L>(nrow0, colA, c0[0], c0[1]);
                if (colB < 300) store_pair<L>(nrow0, colB, c1[0], c1[1]);
            }
            if (nrow1 < NN) {
                store_pair<L>(nrow1, colA, c0[2], c0[3]);
                if (colB < 300) store_pair<L>(nrow1, colB, c1[2], c1[3]);
            }
        }
    }
}

// ---------------- aggregation: warp per node over CSR, atomic-free, 2-edge unroll --
// L==1: writes g_h (device-side symbol) = mean + rt1 + bias1.
// L==2: writes log_softmax(mean + rt2 + bias2) into `out` (harness d_out).
template <int L>
__global__ void k_agg(const float* __restrict__ bias, float* __restrict__ out) {
    int n = (blockIdx.x * blockDim.x + threadIdx.x) >> 5;
    if (n >= NN) return;
    int lane = threadIdx.x & 31;
    int end = g_woff[n];          // row end after scatter
    int d = g_deg[n];
    int start = end - d;
    const float*   T  = (L == 1) ? g_T1  : g_T2;
    const __half2* XB = (L == 1) ? g_XB1h : g_XB2h;
    const float4*  C4 = (L == 1) ? g_c4a : g_c4b;
    const float*   C1 = (L == 1) ? g_c1a : g_c1b;

    float2 acc  = make_float2(0.f, 0.f);
    float2 acc2 = make_float2(0.f, 0.f);
    int e = start;
    for (; e + 1 < end; e += 2) {
        int2 s0 = __ldg(&g_st[e]);
        int2 s1 = __ldg(&g_st[e + 1]);
        if (lane < 25) {
            float4 ca = __ldg(&C4[s0.y]); float c4a = __ldg(&C1[s0.y]);
            float4 cb = __ldg(&C4[s1.y]); float c4b = __ldg(&C1[s1.y]);
            float2 t0 = __ldg(((const float2*)(T + s0.y * DHID)) + lane);
            float2 t1 = __ldg(((const float2*)(T + s1.y * DHID)) + lane);
            const __half2* x0 = XB + (size_t)s0.x * 125;
            const __half2* x1 = XB + (size_t)s1.x * 125;
            acc.x  += t0.x; acc.y  += t0.y;
            acc2.x += t1.x; acc2.y += t1.y;
            float2 v;
            v = __half22float2(__ldg(x0 + lane));       acc.x  = fmaf(ca.x, v.x, acc.x);  acc.y  = fmaf(ca.x, v.y, acc.y);
            v = __half22float2(__ldg(x1 + lane));       acc2.x = fmaf(cb.x, v.x, acc2.x); acc2.y = fmaf(cb.x, v.y, acc2.y);
            v = __half22float2(__ldg(x0 + 25 + lane));  acc.x  = fmaf(ca.y, v.x, acc.x);  acc.y  = fmaf(ca.y, v.y, acc.y);
            v = __half22float2(__ldg(x1 + 25 + lane));  acc2.x = fmaf(cb.y, v.x, acc2.x); acc2.y = fmaf(cb.y, v.y, acc2.y);
            v = __half22float2(__ldg(x0 + 50 + lane));  acc.x  = fmaf(ca.z, v.x, acc.x);  acc.y  = fmaf(ca.z, v.y, acc.y);
            v = __half22float2(__ldg(x1 + 50 + lane));  acc2.x = fmaf(cb.z, v.x, acc2.x); acc2.y = fmaf(cb.z, v.y, acc2.y);
            v = __half22float2(__ldg(x0 + 75 + lane));  acc.x  = fmaf(ca.w, v.x, acc.x);  acc.y  = fmaf(ca.w, v.y, acc.y);
            v = __half22float2(__ldg(x1 + 75 + lane));  acc2.x = fmaf(cb.w, v.x, acc2.x); acc2.y = fmaf(cb.w, v.y, acc2.y);
            v = __half22float2(__ldg(x0 + 100 + lane)); acc.x  = fmaf(c4a,  v.x, acc.x);  acc.y  = fmaf(c4a,  v.y, acc.y);
            v = __half22float2(__ldg(x1 + 100 + lane)); acc2.x = fmaf(c4b,  v.x, acc2.x); acc2.y = fmaf(c4b,  v.y, acc2.y);
        }
    }
    if (e < end) {
        int2 s0 = __ldg(&g_st[e]);
        if (lane < 25) {
            float4 ca = __ldg(&C4[s0.y]); float c4a = __ldg(&C1[s0.y]);
            float2 t0 = __ldg(((const float2*)(T + s0.y * DHID)) + lane);
            const __half2* x0 = XB + (size_t)s0.x * 125;
            acc.x += t0.x; acc.y += t0.y;
            float2 v;
            v = __half22float2(__ldg(x0 + lane));       acc.x = fmaf(ca.x, v.x, acc.x); acc.y = fmaf(ca.x, v.y, acc.y);
            v = __half22float2(__ldg(x0 + 25 + lane));  acc.x = fmaf(ca.y, v.x, acc.x); acc.y = fmaf(ca.y, v.y, acc.y);
            v = __half22float2(__ldg(x0 + 50 + lane));  acc.x = fmaf(ca.z, v.x, acc.x); acc.y = fmaf(ca.z, v.y, acc.y);
            v = __half22float2(__ldg(x0 + 75 + lane));  acc.x = fmaf(ca.w, v.x, acc.x); acc.y = fmaf(ca.w, v.y, acc.y);
            v = __half22float2(__ldg(x0 + 100 + lane)); acc.x = fmaf(c4a,  v.x, acc.x); acc.y = fmaf(c4a,  v.y, acc.y);
        }
    }
    acc.x += acc2.x; acc.y += acc2.y;

    float cn = fmaxf((float)d, 1.0f);
    if (L == 1) {
        if (lane < 25) {
            float2 r  = __ldg(((const float2*)(g_rt1 + (size_t)n * DHID)) + lane);
            float2 bb = __ldg(((const float2*)bias) + lane);
            ((float2*)(g_h + (size_t)n * DHID))[lane] =
                make_float2(acc.x / cn + r.x + bb.x, acc.y / cn + r.y + bb.y);
        }
    } else {
        float vx = -1e30f, vy = -1e30f;
        if (lane < 25) {
            float2 r  = __ldg(((const float2*)(g_rt2 + (size_t)n * DHID)) + lane);
            float2 bb = __ldg(((const float2*)bias) + lane);
            vx = acc.x / cn + r.x + bb.x;
            vy = acc.y / cn + r.y + bb.y;
        }
        float m = fmaxf(vx, vy);
#pragma unroll
        for (int o = 16; o > 0; o >>= 1) m = fmaxf(m, __shfl_xor_sync(0xFFFFFFFFu, m, o));
        float sacc = (lane < 25) ? (expf(vx - m) + expf(vy - m)) : 0.f;
#pragma unroll
        for (int o = 16; o > 0; o >>= 1) sacc += __shfl_xor_sync(0xFFFFFFFFu, sacc, o);
        float ls = logf(sacc);
        if (lane < 25)
            ((float2*)(out + (size_t)n * DHID))[lane] = make_float2(vx - m - ls, vy - m - ls);
    }
}

// ---------------- launcher ----------------
extern "C" void kernel_launch(void* const* d_in, const int* in_sizes, int n_in,
                              void* d_out, int out_size) {
    const float* x      = (const float*)d_in[0];
    const int*   ei     = (const int*)d_in[1];
    const int*   etype  = (const int*)d_in[2];
    const int*   tgt    = (const int*)d_in[3];
    const float* relE   = (const float*)d_in[4];
    const float* relW   = (const float*)d_in[5];
    const float* basis1 = (const float*)d_in[6];
    const float* comp1  = (const float*)d_in[7];
    const float* root1  = (const float*)d_in[8];
    const float* bias1  = (const float*)d_in[9];
    const float* basis2 = (const float*)d_in[10];
    const float* comp2  = (const float*)d_in[11];
    const float* root2  = (const float*)d_in[12];
    const float* bias2  = (const float*)d_in[13];
    float* out = (float*)d_out;
    int E = in_sizes[1] / 2;

    constexpr int SM1 = (104 * NW + 128 * 108) * (int)sizeof(uint32_t);  // 185,088 B
    constexpr int SM2 = (56 * NW + 128 * 60) * (int)sizeof(uint32_t);    // 100,608 B
    cudaFuncSetAttribute(k_gemm_t<DIN, 1>, cudaFuncAttributeMaxDynamicSharedMemorySize, SM1);
    cudaFuncSetAttribute(k_gemm_t<DHID, 2>, cudaFuncAttributeMaxDynamicSharedMemorySize, SM2);

    // CSR build (reused by both layers)
    k_zero<<<(NN + 255) / 256, 256>>>();
    k_tables<<<NRT, 64>>>(relE, relW, basis1, comp1, basis2, comp2);
    k_hist<<<(E + 255) / 256, 256>>>(ei, E);
    k_scan1<<<NCH, SCAN_CH>>>();
    k_scan2<<<1, 256>>>();
    k_scan3<<<(NN + 255) / 256, 256>>>();
    k_scatter<<<(E + 255) / 256, 256>>>(ei, etype, E);

    // layer 1 (tf32 tensor GEMM, persistent)
    k_gemm_t<DIN, 1><<<148, 256, SM1>>>(x, basis1, root1, tgt);
    k_agg<1><<<(NN + 7) / 8, 256>>>(bias1, nullptr);
    // layer 2 (2 blocks/SM)
    k_gemm_t<DHID, 2><<<296, 256, SM2>>>(x /*unused*/, basis2, root2, nullptr);
    k_agg<2><<<(NN + 7) / 8, 256>>>(bias2, out);
}

// round 12
// speedup vs baseline: 2.1204x; 1.1455x over previous
#include <cuda_runtime.h>
#include <cuda_fp16.h>
#include <math.h>
#include <stdint.h>

#define NN 100000        // nodes
#define NE 1600000       // edges (fixed problem shape)
#define DIN 100
#define DHID 50
#define NRT 474          // doubled relation types
#define NB 5             // bases
#define SCAN_CH 512
#define NCH ((NN + SCAN_CH - 1) / SCAN_CH)   // 196
#define NT128 ((NN + 127) / 128)             // 782 node tiles of 128
#define NW 312                               // padded W smem row stride (words)
static_assert(NCH <= 256, "scan2 assumes <=256 chunks");

// ---------------- scratch (device globals; no allocation allowed) ----------------
__device__ __half2 g_XB1h[(size_t)NN * 125];   // fp16 gather tables, 50 MB each
__device__ __half2 g_XB2h[(size_t)NN * 125];
__device__ float g_rt1[(size_t)NN * DHID];     // x @ root1 (fp32)
__device__ float g_rt2[(size_t)NN * DHID];     // h @ root2 (fp32)
__device__ float g_h[(size_t)NN * DHID];
__device__ float g_T1[NRT * DHID];
__device__ float g_T2[NRT * DHID];
__device__ float4 g_c4a[NRT]; __device__ float g_c1a[NRT];   // comp1 split
__device__ float4 g_c4b[NRT]; __device__ float g_c1b[NRT];   // comp2 split
// CSR scratch
__device__ int  g_deg[NN];
__device__ int  g_woff[NN];      // exclusive scan; scatter mutates to row END
__device__ int  g_part[256];
__device__ int2 g_st[NE];        // dst-sorted (src, type)

// ---------------- zero degree ----------------
__global__ void k_zero() {
    int i = blockIdx.x * blockDim.x + threadIdx.x;
    if (i < NN) g_deg[i] = 0;
}

// ---------------- histogram over dst ----------------
__global__ void k_hist(const int* __restrict__ ei, int E) {
    int e = blockIdx.x * blockDim.x + threadIdx.x;
    if (e < E) atomicAdd(&g_deg[ei[E + e]], 1);
}

// ---------------- scan phase 1: per-chunk exclusive scan ----------------
__global__ void k_scan1() {
    __shared__ int s[SCAN_CH];
    int t = threadIdx.x, i = blockIdx.x * SCAN_CH + t;
    int v = (i < NN) ? g_deg[i] : 0;
    s[t] = v;
    __syncthreads();
#pragma unroll
    for (int off = 1; off < SCAN_CH; off <<= 1) {
        int x = (t >= off) ? s[t - off] : 0;
        __syncthreads();
        s[t] += x;
        __syncthreads();
    }
    if (i < NN) g_woff[i] = s[t] - v;          // exclusive
    if (t == SCAN_CH - 1) g_part[blockIdx.x] = s[t];
}

// ---------------- scan phase 2: scan chunk totals (1 block) ----------------
__global__ void k_scan2() {
    __shared__ int s[256];
    int t = threadIdx.x;
    int v = (t < NCH) ? g_part[t] : 0;
    s[t] = v;
    __syncthreads();
#pragma unroll
    for (int off = 1; off < 256; off <<= 1) {
        int x = (t >= off) ? s[t - off] : 0;
        __syncthreads();
        s[t] += x;
        __syncthreads();
    }
    if (t < NCH) g_part[t] = s[t] - v;         // exclusive
}

// ---------------- scan phase 3: add chunk base ----------------
__global__ void k_scan3() {
    int i = blockIdx.x * blockDim.x + threadIdx.x;
    if (i < NN) g_woff[i] += g_part[i / SCAN_CH];
}

// ---------------- scatter edges into CSR (ticket order within bin) ----------------
__global__ void k_scatter(const int* __restrict__ ei, const int* __restrict__ etype, int E) {
    int e = blockIdx.x * blockDim.x + threadIdx.x;
    if (e >= E) return;
    int src = ei[e], dst = ei[E + e], t = etype[e];
    int pos = atomicAdd(&g_woff[dst], 1);
    g_st[pos] = make_int2(src, t);
}

// ---------------- per-relation-type tables ----------------
__global__ void k_tables(const float* __restrict__ relE, const float* __restrict__ relW,
                         const float* __restrict__ basis1, const float* __restrict__ comp1,
                         const float* __restrict__ basis2, const float* __restrict__ comp2) {
    int et = blockIdx.x;               // 0..473
    int r = (et < 237) ? et : et - 237;
    __shared__ float sE[DIN];
    __shared__ float sR2[DHID];
    int tid = threadIdx.x;             // 64 threads
    for (int k = tid; k < DIN; k += blockDim.x) sE[k] = relE[r * DIN + k];
    if (tid == 0) {
        g_c4a[et] = make_float4(comp1[et*NB+0], comp1[et*NB+1], comp1[et*NB+2], comp1[et*NB+3]);
        g_c1a[et] = comp1[et*NB+4];
        g_c4b[et] = make_float4(comp2[et*NB+0], comp2[et*NB+1], comp2[et*NB+2], comp2[et*NB+3]);
        g_c1b[et] = comp2[et*NB+4];
    }
    __syncthreads();
    if (tid < DHID) {
        int j = tid;
        float sb[NB] = {0, 0, 0, 0, 0};
        float r2 = 0.f;
        for (int k = 0; k < DIN; k++) {
            float e = sE[k];
#pragma unroll
            for (int b = 0; b < NB; b++)
                sb[b] = fmaf(e, basis1[((size_t)b * DIN + k) * DHID + j], sb[b]);
            r2 = fmaf(e, relW[k * DHID + j], r2);
        }
        float t1 = 0.f;
#pragma unroll
        for (int b = 0; b < NB; b++) t1 = fmaf(comp1[et * NB + b], sb[b], t1);
        g_T1[et * DHID + j] = t1;
        sR2[j] = r2;
    }
    __syncthreads();
    if (tid < DHID) {
        int j = tid;
        float sb[NB] = {0, 0, 0, 0, 0};
        for (int k = 0; k < DHID; k++) {
            float e = sR2[k];
#pragma unroll
            for (int b = 0; b < NB; b++)
                sb[b] = fmaf(e, basis2[((size_t)b * DHID + k) * DHID + j], sb[b]);
        }
        float t2 = 0.f;
#pragma unroll
        for (int b = 0; b < NB; b++) t2 = fmaf(comp2[et * NB + b], sb[b], t2);
        g_T2[et * DHID + j] = t2;
    }
}

// ---------------- tf32 helpers ----------------
__device__ __forceinline__ uint32_t f2tf32(float v) {
    uint32_t t;
    asm("cvt.rna.tf32.f32 %0, %1;" : "=r"(t) : "f"(v));
    return t;
}
__device__ __forceinline__ void mma_tf32(float c[4], const uint32_t a[4],
                                         uint32_t b0, uint32_t b1) {
    asm volatile(
        "mma.sync.aligned.m16n8k8.row.col.f32.tf32.tf32.f32 "
        "{%0,%1,%2,%3}, {%4,%5,%6,%7}, {%8,%9}, {%0,%1,%2,%3};"
        : "+f"(c[0]), "+f"(c[1]), "+f"(c[2]), "+f"(c[3])
        : "r"(a[0]), "r"(a[1]), "r"(a[2]), "r"(a[3]), "r"(b0), "r"(b1));
}

// pairwise store into the split output (col even)
template <int L>
__device__ __forceinline__ void store_pair(int n, int col, float vA, float vB) {
    float*   outR = (L == 1) ? g_rt1 : g_rt2;
    __half2* outB = (L == 1) ? g_XB1h : g_XB2h;
    if (col < 50) {
        *(float2*)&outR[(size_t)n * DHID + col] = make_float2(vA, vB);
    } else {
        int b = (col - 50) / 50, j = (col - 50) - b * 50;   // j even
        outB[(size_t)n * 125 + b * 25 + (j >> 1)] = __floats2half2_rn(vA, vB);
    }
}

// ---------------- tensor-core node GEMM (tf32 mma.sync) ----------------
template <int K, int L>
__global__ void __launch_bounds__(256, (L == 1) ? 1 : 2)
k_gemm_t(const float* __restrict__ A_in, const float* __restrict__ basisW,
         const float* __restrict__ rootW, const int* __restrict__ targetPtr) {
    constexpr int KT = (K + 7) / 8;      // 13 / 7 k-tiles
    constexpr int KP = KT * 8;           // 104 / 56
    constexpr int KS = KP + 4;           // padded A row stride: 108 / 60 (bank-clean)
    extern __shared__ uint32_t smu[];
    uint32_t* sW = smu;                  // [KP][NW]
    uint32_t* sA = smu + KP * NW;        // [128][KS]
    const float* A = (L == 1) ? A_in : g_h;

    int tid = threadIdx.x;
    int target = (L == 1) ? *targetPtr : -1;

    // stage W once (tf32 bits; zero padding)
    for (int idx = tid; idx < KP * NW; idx += 256) {
        int k = idx / NW, c = idx - k * NW;
        float v = 0.f;
        if (k < K && c < 300) {
            if (c < 50) v = rootW[k * DHID + c];
            else { int b = (c - 50) / 50, j = (c - 50) - b * 50;
                   v = basisW[((size_t)b * K + k) * DHID + j]; }
        }
        sW[idx] = f2tf32(v);
    }

    int lane = tid & 31, warp = tid >> 5;
    int gid = lane >> 2, tig = lane & 3;
    int wr = warp * 16;

    for (int t = blockIdx.x; t < NT128; t += gridDim.x) {
        int n0 = t * 128;
        __syncthreads();   // prev-iter compute done (also covers W staging, iter 0)
        for (int idx = tid; idx < 128 * KS; idx += 256) {
            int i = idx / KS, k = idx - i * KS;
            int n = n0 + i;
            float v = 0.f;
            if (k < K && n < NN && n != target) v = A[(size_t)n * K + k];
            sA[idx] = f2tf32(v);
        }
        __syncthreads();

        // A fragments for this warp's 16 rows, all k-tiles
        uint32_t aF[KT][4];
#pragma unroll
        for (int kt = 0; kt < KT; kt++) {
            int r0 = (wr + gid) * KS, r1 = (wr + gid + 8) * KS;
            int kk = kt * 8 + tig;
            aF[kt][0] = sA[r0 + kk];
            aF[kt][1] = sA[r1 + kk];
            aF[kt][2] = sA[r0 + kk + 4];
            aF[kt][3] = sA[r1 + kk + 4];
        }

        int nrow0 = n0 + wr + gid;
        int nrow1 = nrow0 + 8;
        for (int nt = 0; nt < 38; nt += 2) {
            float c0[4] = {0.f, 0.f, 0.f, 0.f};
            float c1[4] = {0.f, 0.f, 0.f, 0.f};
            int nb = nt * 8 + gid;
#pragma unroll
            for (int kt = 0; kt < KT; kt++) {
                int kb = kt * 8 + tig;
                uint32_t b0a = sW[kb * NW + nb];
                uint32_t b1a = sW[(kb + 4) * NW + nb];
                uint32_t b0b = sW[kb * NW + nb + 8];
                uint32_t b1b = sW[(kb + 4) * NW + nb + 8];
                mma_tf32(c0, aF[kt], b0a, b1a);
                mma_tf32(c1, aF[kt], b0b, b1b);
            }
            int colA = nt * 8 + tig * 2;       // even
            int colB = colA + 8;
            if (nrow0 < NN) {
                store_pair<L>(nrow0, colA, c0[0], c0[1]);
                if (colB < 300) store_pair<L>(nrow0, colB, c1[0], c1[1]);
            }
            if (nrow1 < NN) {
                store_pair<L>(nrow1, colA, c0[2], c0[3]);
                if (colB < 300) store_pair<L>(nrow1, colB, c1[2], c1[3]);
            }
        }
    }
}

// ---------------- per-edge accumulate helper ----------------
template <int L>
__device__ __forceinline__ void edge_acc(int2 st, int lane, float2& acc) {
    const float*   T  = (L == 1) ? g_T1  : g_T2;
    const __half2* XB = (L == 1) ? g_XB1h : g_XB2h;
    const float4*  C4 = (L == 1) ? g_c4a : g_c4b;
    const float*   C1 = (L == 1) ? g_c1a : g_c1b;
    float4 c  = __ldg(&C4[st.y]);
    float  c4 = __ldg(&C1[st.y]);
    float2 tv = __ldg(((const float2*)(T + st.y * DHID)) + lane);
    const __half2* xr = XB + (size_t)st.x * 125;
    float2 v0 = __half22float2(__ldg(xr + lane));
    float2 v1 = __half22float2(__ldg(xr + 25 + lane));
    float2 v2 = __half22float2(__ldg(xr + 50 + lane));
    float2 v3 = __half22float2(__ldg(xr + 75 + lane));
    float2 v4 = __half22float2(__ldg(xr + 100 + lane));
    acc.x += tv.x; acc.y += tv.y;
    acc.x = fmaf(c.x, v0.x, acc.x); acc.y = fmaf(c.x, v0.y, acc.y);
    acc.x = fmaf(c.y, v1.x, acc.x); acc.y = fmaf(c.y, v1.y, acc.y);
    acc.x = fmaf(c.z, v2.x, acc.x); acc.y = fmaf(c.z, v2.y, acc.y);
    acc.x = fmaf(c.w, v3.x, acc.x); acc.y = fmaf(c.w, v3.y, acc.y);
    acc.x = fmaf(c4,  v4.x, acc.x); acc.y = fmaf(c4,  v4.y, acc.y);
}

// ---------------- aggregation: warp per node over CSR, atomic-free, 4-edge unroll --
template <int L>
__global__ void k_agg(const float* __restrict__ bias, float* __restrict__ out) {
    int n = (blockIdx.x * blockDim.x + threadIdx.x) >> 5;
    if (n >= NN) return;
    int lane = threadIdx.x & 31;
    int end = g_woff[n];          // row end after scatter
    int d = g_deg[n];
    int start = end - d;

    float2 a0 = make_float2(0.f, 0.f), a1 = a0, a2 = a0, a3 = a0;
    int e = start;
    for (; e + 3 < end; e += 4) {
        int2 s0 = __ldg(&g_st[e]);
        int2 s1 = __ldg(&g_st[e + 1]);
        int2 s2 = __ldg(&g_st[e + 2]);
        int2 s3 = __ldg(&g_st[e + 3]);
        if (lane < 25) {
            edge_acc<L>(s0, lane, a0);
            edge_acc<L>(s1, lane, a1);
            edge_acc<L>(s2, lane, a2);
            edge_acc<L>(s3, lane, a3);
        }
    }
    for (; e < end; e++) {
        int2 s0 = __ldg(&g_st[e]);
        if (lane < 25) edge_acc<L>(s0, lane, a0);
    }
    float2 acc = make_float2(a0.x + a1.x + a2.x + a3.x, a0.y + a1.y + a2.y + a3.y);

    float cn = fmaxf((float)d, 1.0f);
    if (L == 1) {
        if (lane < 25) {
            float2 r  = __ldg(((const float2*)(g_rt1 + (size_t)n * DHID)) + lane);
            float2 bb = __ldg(((const float2*)bias) + lane);
            ((float2*)(g_h + (size_t)n * DHID))[lane] =
                make_float2(acc.x / cn + r.x + bb.x, acc.y / cn + r.y + bb.y);
        }
    } else {
        float vx = -1e30f, vy = -1e30f;
        if (lane < 25) {
            float2 r  = __ldg(((const float2*)(g_rt2 + (size_t)n * DHID)) + lane);
            float2 bb = __ldg(((const float2*)bias) + lane);
            vx = acc.x / cn + r.x + bb.x;
            vy = acc.y / cn + r.y + bb.y;
        }
        float m = fmaxf(vx, vy);
#pragma unroll
        for (int o = 16; o > 0; o >>= 1) m = fmaxf(m, __shfl_xor_sync(0xFFFFFFFFu, m, o));
        float sacc = (lane < 25) ? (expf(vx - m) + expf(vy - m)) : 0.f;
#pragma unroll
        for (int o = 16; o > 0; o >>= 1) sacc += __shfl_xor_sync(0xFFFFFFFFu, sacc, o);
        float ls = logf(sacc);
        if (lane < 25)
            ((float2*)(out + (size_t)n * DHID))[lane] = make_float2(vx - m - ls, vy - m - ls);
    }
}

// ---------------- launcher ----------------
extern "C" void kernel_launch(void* const* d_in, const int* in_sizes, int n_in,
                              void* d_out, int out_size) {
    const float* x      = (const float*)d_in[0];
    const int*   ei     = (const int*)d_in[1];
    const int*   etype  = (const int*)d_in[2];
    const int*   tgt    = (const int*)d_in[3];
    const float* relE   = (const float*)d_in[4];
    const float* relW   = (const float*)d_in[5];
    const float* basis1 = (const float*)d_in[6];
    const float* comp1  = (const float*)d_in[7];
    const float* root1  = (const float*)d_in[8];
    const float* bias1  = (const float*)d_in[9];
    const float* basis2 = (const float*)d_in[10];
    const float* comp2  = (const float*)d_in[11];
    const float* root2  = (const float*)d_in[12];
    const float* bias2  = (const float*)d_in[13];
    float* out = (float*)d_out;
    int E = in_sizes[1] / 2;

    constexpr int SM1 = (104 * NW + 128 * 108) * (int)sizeof(uint32_t);  // 185,088 B
    constexpr int SM2 = (56 * NW + 128 * 60) * (int)sizeof(uint32_t);    // 100,608 B
    cudaFuncSetAttribute(k_gemm_t<DIN, 1>, cudaFuncAttributeMaxDynamicSharedMemorySize, SM1);
    cudaFuncSetAttribute(k_gemm_t<DHID, 2>, cudaFuncAttributeMaxDynamicSharedMemorySize, SM2);

    // launch order chosen so the profiler's sampled launch (index 3) is gemm1
    k_zero<<<(NN + 255) / 256, 256>>>();                       // 0
    k_hist<<<(E + 255) / 256, 256>>>(ei, E);                   // 1
    k_tables<<<NRT, 64>>>(relE, relW, basis1, comp1, basis2, comp2);  // 2
    k_gemm_t<DIN, 1><<<148, 256, SM1>>>(x, basis1, root1, tgt);       // 3 <- profiled
    k_scan1<<<NCH, SCAN_CH>>>();                               // 4
    k_scan2<<<1, 256>>>();                                     // 5
    k_scan3<<<(NN + 255) / 256, 256>>>();                      // 6
    k_scatter<<<(E + 255) / 256, 256>>>(ei, etype, E);         // 7
    k_agg<1><<<(NN + 7) / 8, 256>>>(bias1, nullptr);           // 8
    k_gemm_t<DHID, 2><<<296, 256, SM2>>>(x /*unused*/, basis2, root2, nullptr);  // 9
    k_agg<2><<<(NN + 7) / 8, 256>>>(bias2, out);               // 10
}

// round 13
// speedup vs baseline: 2.3730x; 1.1192x over previous
#include <cuda_runtime.h>
#include <cuda_fp16.h>
#include <math.h>
#include <stdint.h>

#define NN 100000        // nodes
#define NE 1600000       // edges (fixed problem shape)
#define DIN 100
#define DHID 50
#define NRT 474          // doubled relation types
#define NB 5             // bases
#define SCAN_CH 512
#define NCH ((NN + SCAN_CH - 1) / SCAN_CH)   // 196
#define NT128 ((NN + 127) / 128)             // 782 node tiles of 128
#define NW 312                               // padded W smem row stride (words)
static_assert(NCH <= 256, "scan2 assumes <=256 chunks");

// ---------------- scratch (device globals; no allocation allowed) ----------------
__device__ __half2 g_XB1h[(size_t)NN * 125];   // fp16 gather tables, 50 MB each
__device__ __half2 g_XB2h[(size_t)NN * 125];
__device__ float g_rt1[(size_t)NN * DHID];     // x @ root1 (fp32)
__device__ float g_rt2[(size_t)NN * DHID];     // h @ root2 (fp32)
__device__ float g_h[(size_t)NN * DHID];
__device__ float g_T1[NRT * DHID];
__device__ float g_T2[NRT * DHID];
__device__ float4 g_c4a[NRT]; __device__ float g_c1a[NRT];   // comp1 split
__device__ float4 g_c4b[NRT]; __device__ float g_c1b[NRT];   // comp2 split
// CSR scratch
__device__ int  g_deg[NN];
__device__ int  g_woff[NN];      // exclusive scan; scatter mutates to row END
__device__ int  g_part[256];
__device__ int2 g_st[NE];        // dst-sorted (src, type)

// ---------------- zero degree ----------------
__global__ void k_zero() {
    int i = blockIdx.x * blockDim.x + threadIdx.x;
    if (i < NN) g_deg[i] = 0;
}

// ---------------- histogram over dst ----------------
__global__ void k_hist(const int* __restrict__ ei, int E) {
    int e = blockIdx.x * blockDim.x + threadIdx.x;
    if (e < E) atomicAdd(&g_deg[ei[E + e]], 1);
}

// ---------------- scan phase 1: per-chunk exclusive scan ----------------
__global__ void k_scan1() {
    __shared__ int s[SCAN_CH];
    int t = threadIdx.x, i = blockIdx.x * SCAN_CH + t;
    int v = (i < NN) ? g_deg[i] : 0;
    s[t] = v;
    __syncthreads();
#pragma unroll
    for (int off = 1; off < SCAN_CH; off <<= 1) {
        int x = (t >= off) ? s[t - off] : 0;
        __syncthreads();
        s[t] += x;
        __syncthreads();
    }
    if (i < NN) g_woff[i] = s[t] - v;          // exclusive
    if (t == SCAN_CH - 1) g_part[blockIdx.x] = s[t];
}

// ---------------- scan phase 2: scan chunk totals (1 block) ----------------
__global__ void k_scan2() {
    __shared__ int s[256];
    int t = threadIdx.x;
    int v = (t < NCH) ? g_part[t] : 0;
    s[t] = v;
    __syncthreads();
#pragma unroll
    for (int off = 1; off < 256; off <<= 1) {
        int x = (t >= off) ? s[t - off] : 0;
        __syncthreads();
        s[t] += x;
        __syncthreads();
    }
    if (t < NCH) g_part[t] = s[t] - v;         // exclusive
}

// ---------------- scan phase 3: add chunk base ----------------
__global__ void k_scan3() {
    int i = blockIdx.x * blockDim.x + threadIdx.x;
    if (i < NN) g_woff[i] += g_part[i / SCAN_CH];
}

// ---------------- scatter edges into CSR (ticket order within bin) ----------------
__global__ void k_scatter(const int* __restrict__ ei, const int* __restrict__ etype, int E) {
    int e = blockIdx.x * blockDim.x + threadIdx.x;
    if (e >= E) return;
    int src = ei[e], dst = ei[E + e], t = etype[e];
    int pos = atomicAdd(&g_woff[dst], 1);
    g_st[pos] = make_int2(src, t);
}

// ---------------- per-relation-type tables ----------------
__global__ void k_tables(const float* __restrict__ relE, const float* __restrict__ relW,
                         const float* __restrict__ basis1, const float* __restrict__ comp1,
                         const float* __restrict__ basis2, const float* __restrict__ comp2) {
    int et = blockIdx.x;               // 0..473
    int r = (et < 237) ? et : et - 237;
    __shared__ float sE[DIN];
    __shared__ float sR2[DHID];
    int tid = threadIdx.x;             // 64 threads
    for (int k = tid; k < DIN; k += blockDim.x) sE[k] = relE[r * DIN + k];
    if (tid == 0) {
        g_c4a[et] = make_float4(comp1[et*NB+0], comp1[et*NB+1], comp1[et*NB+2], comp1[et*NB+3]);
        g_c1a[et] = comp1[et*NB+4];
        g_c4b[et] = make_float4(comp2[et*NB+0], comp2[et*NB+1], comp2[et*NB+2], comp2[et*NB+3]);
        g_c1b[et] = comp2[et*NB+4];
    }
    __syncthreads();
    if (tid < DHID) {
        int j = tid;
        float sb[NB] = {0, 0, 0, 0, 0};
        float r2 = 0.f;
        for (int k = 0; k < DIN; k++) {
            float e = sE[k];
#pragma unroll
            for (int b = 0; b < NB; b++)
                sb[b] = fmaf(e, basis1[((size_t)b * DIN + k) * DHID + j], sb[b]);
            r2 = fmaf(e, relW[k * DHID + j], r2);
        }
        float t1 = 0.f;
#pragma unroll
        for (int b = 0; b < NB; b++) t1 = fmaf(comp1[et * NB + b], sb[b], t1);
        g_T1[et * DHID + j] = t1;
        sR2[j] = r2;
    }
    __syncthreads();
    if (tid < DHID) {
        int j = tid;
        float sb[NB] = {0, 0, 0, 0, 0};
        for (int k = 0; k < DHID; k++) {
            float e = sR2[k];
#pragma unroll
            for (int b = 0; b < NB; b++)
                sb[b] = fmaf(e, basis2[((size_t)b * DHID + k) * DHID + j], sb[b]);
        }
        float t2 = 0.f;
#pragma unroll
        for (int b = 0; b < NB; b++) t2 = fmaf(comp2[et * NB + b], sb[b], t2);
        g_T2[et * DHID + j] = t2;
    }
}

// ---------------- tf32 helpers ----------------
__device__ __forceinline__ uint32_t f2tf32(float v) {
    uint32_t t;
    asm("cvt.rna.tf32.f32 %0, %1;" : "=r"(t) : "f"(v));
    return t;
}
__device__ __forceinline__ void mma_tf32(float c[4], const uint32_t a[4],
                                         uint32_t b0, uint32_t b1) {
    asm volatile(
        "mma.sync.aligned.m16n8k8.row.col.f32.tf32.tf32.f32 "
        "{%0,%1,%2,%3}, {%4,%5,%6,%7}, {%8,%9}, {%0,%1,%2,%3};"
        : "+f"(c[0]), "+f"(c[1]), "+f"(c[2]), "+f"(c[3])
        : "r"(a[0]), "r"(a[1]), "r"(a[2]), "r"(a[3]), "r"(b0), "r"(b1));
}

// pairwise store into the split output (col even)
template <int L>
__device__ __forceinline__ void store_pair(int n, int col, float vA, float vB) {
    float*   outR = (L == 1) ? g_rt1 : g_rt2;
    __half2* outB = (L == 1) ? g_XB1h : g_XB2h;
    if (col < 50) {
        *(float2*)&outR[(size_t)n * DHID + col] = make_float2(vA, vB);
    } else {
        int b = (col - 50) / 50, j = (col - 50) - b * 50;   // j even
        outB[(size_t)n * 125 + b * 25 + (j >> 1)] = __floats2half2_rn(vA, vB);
    }
}

// ---------------- tensor-core node GEMM (tf32 mma.sync) ----------------
// 512 threads = 16 warps: warp -> (row-group rg = w>>1, n-half nh = w&1).
// A staged as RAW f32 bits via vector copy (tf32 MMA reads top bits; RZ-vs-RNA only).
// Pad columns [K, KP+4) zeroed once; staging never touches them afterward.
template <int K, int L>
__global__ void __launch_bounds__(512, (L == 1) ? 1 : 2)
k_gemm_t(const float* __restrict__ A_in, const float* __restrict__ basisW,
         const float* __restrict__ rootW, const int* __restrict__ targetPtr) {
    constexpr int KT = (K + 7) / 8;      // 13 / 7 k-tiles
    constexpr int KP = KT * 8;           // 104 / 56
    constexpr int KS = KP + 4;           // padded A row stride: 108 / 60 (bank-clean)
    constexpr int VEC = (K == 100) ? 4 : 2;   // A rows: 400B -> float4, 200B -> float2
    constexpr int CHUNKS = K / VEC;      // 25 per row, both layers
    extern __shared__ uint32_t smu[];
    uint32_t* sW = smu;                  // [KP][NW]
    uint32_t* sA = smu + KP * NW;        // [128][KS]
    const float* A = (L == 1) ? A_in : g_h;

    int tid = threadIdx.x;
    int target = (L == 1) ? *targetPtr : -1;

    // stage W once (tf32 bits via cvt.rna; zero padding)
    for (int idx = tid; idx < KP * NW; idx += 512) {
        int k = idx / NW, c = idx - k * NW;
        float v = 0.f;
        if (k < K && c < 300) {
            if (c < 50) v = rootW[k * DHID + c];
            else { int b = (c - 50) / 50, j = (c - 50) - b * 50;
                   v = basisW[((size_t)b * K + k) * DHID + j]; }
        }
        sW[idx] = f2tf32(v);
    }
    // zero the A pad columns once (never rewritten by staging)
    for (int idx = tid; idx < 128 * (KS - K); idx += 512) {
        int i = idx / (KS - K), k = K + idx - i * (KS - K);
        sA[i * KS + k] = 0u;
    }

    int lane = tid & 31, warp = tid >> 5;
    int gid = lane >> 2, tig = lane & 3;
    int rg = warp >> 1, nh = warp & 1;
    int wr = rg * 16;

    for (int t = blockIdx.x; t < NT128; t += gridDim.x) {
        int n0 = t * 128;
        __syncthreads();   // prev-iter compute done (also covers W/pad staging, iter 0)
        // vectorized raw-bit A staging: 128 rows x CHUNKS vectors
        for (int idx = tid; idx < 128 * CHUNKS; idx += 512) {
            int i = idx / CHUNKS, q = idx - i * CHUNKS;
            int n = n0 + i;
            bool ok = (n < NN) && (n != target);
            if (VEC == 4) {
                float4 v = ok ? *(const float4*)(A + (size_t)n * K + q * 4)
                              : make_float4(0.f, 0.f, 0.f, 0.f);
                *(float4*)&sA[i * KS + q * 4] = v;
            } else {
                float2 v = ok ? *(const float2*)(A + (size_t)n * K + q * 2)
                              : make_float2(0.f, 0.f);
                *(float2*)&sA[i * KS + q * 2] = v;
            }
        }
        __syncthreads();

        // A fragments for this warp's 16 rows, all k-tiles
        uint32_t aF[KT][4];
#pragma unroll
        for (int kt = 0; kt < KT; kt++) {
            int r0 = (wr + gid) * KS, r1 = (wr + gid + 8) * KS;
            int kk = kt * 8 + tig;
            aF[kt][0] = sA[r0 + kk];
            aF[kt][1] = sA[r1 + kk];
            aF[kt][2] = sA[r0 + kk + 4];
            aF[kt][3] = sA[r1 + kk + 4];
        }

        int nrow0 = n0 + wr + gid;
        int nrow1 = nrow0 + 8;
        // n-pairs q=0..18 (pair q covers n-tiles 2q, 2q+1); half nh takes q%2==nh
        for (int q = nh; q < 19; q += 2) {
            int nt = 2 * q;
            float c0[4] = {0.f, 0.f, 0.f, 0.f};
            float c1[4] = {0.f, 0.f, 0.f, 0.f};
            int nb = nt * 8 + gid;
#pragma unroll
            for (int kt = 0; kt < KT; kt++) {
                int kb = kt * 8 + tig;
                uint32_t b0a = sW[kb * NW + nb];
                uint32_t b1a = sW[(kb + 4) * NW + nb];
                uint32_t b0b = sW[kb * NW + nb + 8];
                uint32_t b1b = sW[(kb + 4) * NW + nb + 8];
                mma_tf32(c0, aF[kt], b0a, b1a);
                mma_tf32(c1, aF[kt], b0b, b1b);
            }
            int colA = nt * 8 + tig * 2;       // even
            int colB = colA + 8;
            if (nrow0 < NN) {
                store_pair<L>(nrow0, colA, c0[0], c0[1]);
                if (colB < 300) store_pair<L>(nrow0, colB, c1[0], c1[1]);
            }
            if (nrow1 < NN) {
                store_pair<L>(nrow1, colA, c0[2], c0[3]);
                if (colB < 300) store_pair<L>(nrow1, colB, c1[2], c1[3]);
            }
        }
    }
}

// ---------------- per-edge accumulate helper ----------------
template <int L>
__device__ __forceinline__ void edge_acc(int2 st, int lane, float2& acc) {
    const float*   T  = (L == 1) ? g_T1  : g_T2;
    const __half2* XB = (L == 1) ? g_XB1h : g_XB2h;
    const float4*  C4 = (L == 1) ? g_c4a : g_c4b;
    const float*   C1 = (L == 1) ? g_c1a : g_c1b;
    float4 c  = __ldg(&C4[st.y]);
    float  c4 = __ldg(&C1[st.y]);
    float2 tv = __ldg(((const float2*)(T + st.y * DHID)) + lane);
    const __half2* xr = XB + (size_t)st.x * 125;
    float2 v0 = __half22float2(__ldg(xr + lane));
    float2 v1 = __half22float2(__ldg(xr + 25 + lane));
    float2 v2 = __half22float2(__ldg(xr + 50 + lane));
    float2 v3 = __half22float2(__ldg(xr + 75 + lane));
    float2 v4 = __half22float2(__ldg(xr + 100 + lane));
    acc.x += tv.x; acc.y += tv.y;
    acc.x = fmaf(c.x, v0.x, acc.x); acc.y = fmaf(c.x, v0.y, acc.y);
    acc.x = fmaf(c.y, v1.x, acc.x); acc.y = fmaf(c.y, v1.y, acc.y);
    acc.x = fmaf(c.z, v2.x, acc.x); acc.y = fmaf(c.z, v2.y, acc.y);
    acc.x = fmaf(c.w, v3.x, acc.x); acc.y = fmaf(c.w, v3.y, acc.y);
    acc.x = fmaf(c4,  v4.x, acc.x); acc.y = fmaf(c4,  v4.y, acc.y);
}

// ---------------- aggregation: warp per node over CSR, atomic-free, 4-edge unroll --
template <int L>
__global__ void k_agg(const float* __restrict__ bias, float* __restrict__ out) {
    int n = (blockIdx.x * blockDim.x + threadIdx.x) >> 5;
    if (n >= NN) return;
    int lane = threadIdx.x & 31;
    int end = g_woff[n];          // row end after scatter
    int d = g_deg[n];
    int start = end - d;

    float2 a0 = make_float2(0.f, 0.f), a1 = a0, a2 = a0, a3 = a0;
    int e = start;
    for (; e + 3 < end; e += 4) {
        int2 s0 = __ldg(&g_st[e]);
        int2 s1 = __ldg(&g_st[e + 1]);
        int2 s2 = __ldg(&g_st[e + 2]);
        int2 s3 = __ldg(&g_st[e + 3]);
        if (lane < 25) {
            edge_acc<L>(s0, lane, a0);
            edge_acc<L>(s1, lane, a1);
            edge_acc<L>(s2, lane, a2);
            edge_acc<L>(s3, lane, a3);
        }
    }
    for (; e < end; e++) {
        int2 s0 = __ldg(&g_st[e]);
        if (lane < 25) edge_acc<L>(s0, lane, a0);
    }
    float2 acc = make_float2(a0.x + a1.x + a2.x + a3.x, a0.y + a1.y + a2.y + a3.y);

    float cn = fmaxf((float)d, 1.0f);
    if (L == 1) {
        if (lane < 25) {
            float2 r  = __ldg(((const float2*)(g_rt1 + (size_t)n * DHID)) + lane);
            float2 bb = __ldg(((const float2*)bias) + lane);
            ((float2*)(g_h + (size_t)n * DHID))[lane] =
                make_float2(acc.x / cn + r.x + bb.x, acc.y / cn + r.y + bb.y);
        }
    } else {
        float vx = -1e30f, vy = -1e30f;
        if (lane < 25) {
            float2 r  = __ldg(((const float2*)(g_rt2 + (size_t)n * DHID)) + lane);
            float2 bb = __ldg(((const float2*)bias) + lane);
            vx = acc.x / cn + r.x + bb.x;
            vy = acc.y / cn + r.y + bb.y;
        }
        float m = fmaxf(vx, vy);
#pragma unroll
        for (int o = 16; o > 0; o >>= 1) m = fmaxf(m, __shfl_xor_sync(0xFFFFFFFFu, m, o));
        float sacc = (lane < 25) ? (expf(vx - m) + expf(vy - m)) : 0.f;
#pragma unroll
        for (int o = 16; o > 0; o >>= 1) sacc += __shfl_xor_sync(0xFFFFFFFFu, sacc, o);
        float ls = logf(sacc);
        if (lane < 25)
            ((float2*)(out + (size_t)n * DHID))[lane] = make_float2(vx - m - ls, vy - m - ls);
    }
}

// ---------------- launcher ----------------
extern "C" void kernel_launch(void* const* d_in, const int* in_sizes, int n_in,
                              void* d_out, int out_size) {
    const float* x      = (const float*)d_in[0];
    const int*   ei     = (const int*)d_in[1];
    const int*   etype  = (const int*)d_in[2];
    const int*   tgt    = (const int*)d_in[3];
    const float* relE   = (const float*)d_in[4];
    const float* relW   = (const float*)d_in[5];
    const float* basis1 = (const float*)d_in[6];
    const float* comp1  = (const float*)d_in[7];
    const float* root1  = (const float*)d_in[8];
    const float* bias1  = (const float*)d_in[9];
    const float* basis2 = (const float*)d_in[10];
    const float* comp2  = (const float*)d_in[11];
    const float* root2  = (const float*)d_in[12];
    const float* bias2  = (const float*)d_in[13];
    float* out = (float*)d_out;
    int E = in_sizes[1] / 2;

    constexpr int SM1 = (104 * NW + 128 * 108) * (int)sizeof(uint32_t);  // 185,088 B
    constexpr int SM2 = (56 * NW + 128 * 60) * (int)sizeof(uint32_t);    // 100,608 B
    cudaFuncSetAttribute(k_gemm_t<DIN, 1>, cudaFuncAttributeMaxDynamicSharedMemorySize, SM1);
    cudaFuncSetAttribute(k_gemm_t<DHID, 2>, cudaFuncAttributeMaxDynamicSharedMemorySize, SM2);

    // launch order chosen so the profiler's sampled launch (index 3) is gemm1
    k_zero<<<(NN + 255) / 256, 256>>>();                       // 0
    k_hist<<<(E + 255) / 256, 256>>>(ei, E);                   // 1
    k_tables<<<NRT, 64>>>(relE, relW, basis1, comp1, basis2, comp2);  // 2
    k_gemm_t<DIN, 1><<<148, 512, SM1>>>(x, basis1, root1, tgt);       // 3 <- profiled
    k_scan1<<<NCH, SCAN_CH>>>();                               // 4
    k_scan2<<<1, 256>>>();                                     // 5
    k_scan3<<<(NN + 255) / 256, 256>>>();                      // 6
    k_scatter<<<(E + 255) / 256, 256>>>(ei, etype, E);         // 7
    k_agg<1><<<(NN + 7) / 8, 256>>>(bias1, nullptr);           // 8
    k_gemm_t<DHID, 2><<<296, 512, SM2>>>(x /*unused*/, basis2, root2, nullptr);  // 9
    k_agg<2><<<(NN + 7) / 8, 256>>>(bias2, out);               // 10
}

// round 14
// speedup vs baseline: 2.5734x; 1.0845x over previous
#include <cuda_runtime.h>
#include <cuda_fp16.h>
#include <math.h>
#include <stdint.h>

#define NN 100000        // nodes
#define NE 1600000       // edges (fixed problem shape)
#define DIN 100
#define DHID 50
#define NRT 474          // doubled relation types
#define NB 5             // bases
#define SCAN_CH 512
#define NCH ((NN + SCAN_CH - 1) / SCAN_CH)   // 196
#define NT128 ((NN + 127) / 128)             // 782 node tiles of 128
#define NW 312                               // padded W smem row stride (words)
static_assert(NCH <= 256, "scan2 assumes <=256 chunks");

// ---------------- scratch (device globals; no allocation allowed) ----------------
__device__ __half2 g_XB1h[(size_t)NN * 125];   // fp16 gather tables, 50 MB each
__device__ __half2 g_XB2h[(size_t)NN * 125];
__device__ float g_rt1[(size_t)NN * DHID];     // x @ root1 (fp32)
__device__ float g_rt2[(size_t)NN * DHID];     // h @ root2 (fp32)
__device__ float g_h[(size_t)NN * DHID];
__device__ float g_T1[NRT * DHID];
__device__ float g_T2[NRT * DHID];
__device__ float4 g_c4a[NRT]; __device__ float g_c1a[NRT];   // comp1 split
__device__ float4 g_c4b[NRT]; __device__ float g_c1b[NRT];   // comp2 split
// CSR scratch
__device__ int  g_deg[NN];
__device__ int  g_woff[NN];      // exclusive scan; scatter mutates to row END
__device__ int  g_part[256];
__device__ int2 g_st[NE];        // dst-sorted (src, type)

// ---------------- zero degree ----------------
__global__ void k_zero() {
    int i = blockIdx.x * blockDim.x + threadIdx.x;
    if (i < NN) g_deg[i] = 0;
}

// ---------------- histogram over dst ----------------
__global__ void k_hist(const int* __restrict__ ei, int E) {
    int e = blockIdx.x * blockDim.x + threadIdx.x;
    if (e < E) atomicAdd(&g_deg[ei[E + e]], 1);
}

// ---------------- scan phase 1: per-chunk exclusive scan ----------------
__global__ void k_scan1() {
    __shared__ int s[SCAN_CH];
    int t = threadIdx.x, i = blockIdx.x * SCAN_CH + t;
    int v = (i < NN) ? g_deg[i] : 0;
    s[t] = v;
    __syncthreads();
#pragma unroll
    for (int off = 1; off < SCAN_CH; off <<= 1) {
        int x = (t >= off) ? s[t - off] : 0;
        __syncthreads();
        s[t] += x;
        __syncthreads();
    }
    if (i < NN) g_woff[i] = s[t] - v;          // exclusive
    if (t == SCAN_CH - 1) g_part[blockIdx.x] = s[t];
}

// ---------------- scan phase 2: scan chunk totals (1 block) ----------------
__global__ void k_scan2() {
    __shared__ int s[256];
    int t = threadIdx.x;
    int v = (t < NCH) ? g_part[t] : 0;
    s[t] = v;
    __syncthreads();
#pragma unroll
    for (int off = 1; off < 256; off <<= 1) {
        int x = (t >= off) ? s[t - off] : 0;
        __syncthreads();
        s[t] += x;
        __syncthreads();
    }
    if (t < NCH) g_part[t] = s[t] - v;         // exclusive
}

// ---------------- scan phase 3: add chunk base ----------------
__global__ void k_scan3() {
    int i = blockIdx.x * blockDim.x + threadIdx.x;
    if (i < NN) g_woff[i] += g_part[i / SCAN_CH];
}

// ---------------- scatter edges into CSR (ticket order within bin) ----------------
__global__ void k_scatter(const int* __restrict__ ei, const int* __restrict__ etype, int E) {
    int e = blockIdx.x * blockDim.x + threadIdx.x;
    if (e >= E) return;
    int src = ei[e], dst = ei[E + e], t = etype[e];
    int pos = atomicAdd(&g_woff[dst], 1);
    g_st[pos] = make_int2(src, t);
}

// ---------------- per-relation-type tables ----------------
__global__ void k_tables(const float* __restrict__ relE, const float* __restrict__ relW,
                         const float* __restrict__ basis1, const float* __restrict__ comp1,
                         const float* __restrict__ basis2, const float* __restrict__ comp2) {
    int et = blockIdx.x;               // 0..473
    int r = (et < 237) ? et : et - 237;
    __shared__ float sE[DIN];
    __shared__ float sR2[DHID];
    int tid = threadIdx.x;             // 64 threads
    for (int k = tid; k < DIN; k += blockDim.x) sE[k] = relE[r * DIN + k];
    if (tid == 0) {
        g_c4a[et] = make_float4(comp1[et*NB+0], comp1[et*NB+1], comp1[et*NB+2], comp1[et*NB+3]);
        g_c1a[et] = comp1[et*NB+4];
        g_c4b[et] = make_float4(comp2[et*NB+0], comp2[et*NB+1], comp2[et*NB+2], comp2[et*NB+3]);
        g_c1b[et] = comp2[et*NB+4];
    }
    __syncthreads();
    if (tid < DHID) {
        int j = tid;
        float sb[NB] = {0, 0, 0, 0, 0};
        float r2 = 0.f;
        for (int k = 0; k < DIN; k++) {
            float e = sE[k];
#pragma unroll
            for (int b = 0; b < NB; b++)
                sb[b] = fmaf(e, basis1[((size_t)b * DIN + k) * DHID + j], sb[b]);
            r2 = fmaf(e, relW[k * DHID + j], r2);
        }
        float t1 = 0.f;
#pragma unroll
        for (int b = 0; b < NB; b++) t1 = fmaf(comp1[et * NB + b], sb[b], t1);
        g_T1[et * DHID + j] = t1;
        sR2[j] = r2;
    }
    __syncthreads();
    if (tid < DHID) {
        int j = tid;
        float sb[NB] = {0, 0, 0, 0, 0};
        for (int k = 0; k < DHID; k++) {
            float e = sR2[k];
#pragma unroll
            for (int b = 0; b < NB; b++)
                sb[b] = fmaf(e, basis2[((size_t)b * DHID + k) * DHID + j], sb[b]);
        }
        float t2 = 0.f;
#pragma unroll
        for (int b = 0; b < NB; b++) t2 = fmaf(comp2[et * NB + b], sb[b], t2);
        g_T2[et * DHID + j] = t2;
    }
}

// ---------------- tf32 / cp.async helpers ----------------
__device__ __forceinline__ uint32_t f2tf32(float v) {
    uint32_t t;
    asm("cvt.rna.tf32.f32 %0, %1;" : "=r"(t) : "f"(v));
    return t;
}
__device__ __forceinline__ void mma_tf32(float c[4], const uint32_t a[4],
                                         uint32_t b0, uint32_t b1) {
    asm volatile(
        "mma.sync.aligned.m16n8k8.row.col.f32.tf32.tf32.f32 "
        "{%0,%1,%2,%3}, {%4,%5,%6,%7}, {%8,%9}, {%0,%1,%2,%3};"
        : "+f"(c[0]), "+f"(c[1]), "+f"(c[2]), "+f"(c[3])
        : "r"(a[0]), "r"(a[1]), "r"(a[2]), "r"(a[3]), "r"(b0), "r"(b1));
}
__device__ __forceinline__ uint32_t smem_u32(const void* p) {
    return (uint32_t)__cvta_generic_to_shared(p);
}
__device__ __forceinline__ void cpa16(uint32_t dst, const void* src, bool pred) {
    int sz = pred ? 16 : 0;
    asm volatile("cp.async.cg.shared.global [%0], [%1], 16, %2;"
                 :: "r"(dst), "l"(src), "r"(sz));
}
__device__ __forceinline__ void cpa8(uint32_t dst, const void* src, bool pred) {
    int sz = pred ? 8 : 0;
    asm volatile("cp.async.ca.shared.global [%0], [%1], 8, %2;"
                 :: "r"(dst), "l"(src), "r"(sz));
}
__device__ __forceinline__ void cpa_commit() {
    asm volatile("cp.async.commit_group;");
}
__device__ __forceinline__ void cpa_wait0() {
    asm volatile("cp.async.wait_group 0;");
}

// pairwise store into the split output (col even)
template <int L>
__device__ __forceinline__ void store_pair(int n, int col, float vA, float vB) {
    float*   outR = (L == 1) ? g_rt1 : g_rt2;
    __half2* outB = (L == 1) ? g_XB1h : g_XB2h;
    if (col < 50) {
        *(float2*)&outR[(size_t)n * DHID + col] = make_float2(vA, vB);
    } else {
        int b = (col - 50) / 50, j = (col - 50) - b * 50;   // j even
        outB[(size_t)n * 125 + b * 25 + (j >> 1)] = __floats2half2_rn(vA, vB);
    }
}

// ---------------- tensor-core node GEMM (tf32 mma.sync, cp.async pipelined) -------
// 512 threads = 16 warps: warp -> (row-group rg = w>>1, n-half nh = w&1).
// Single A buffer: frags go smem->regs right after arrival, then next tile's
// cp.async overlaps the whole MMA/store phase.
template <int K, int L>
__global__ void __launch_bounds__(512, (L == 1) ? 1 : 2)
k_gemm_t(const float* __restrict__ A_in, const float* __restrict__ basisW,
         const float* __restrict__ rootW, const int* __restrict__ targetPtr) {
    constexpr int KT = (K + 7) / 8;      // 13 / 7 k-tiles
    constexpr int KP = KT * 8;           // 104 / 56
    constexpr int KS = KP + 4;           // padded A row stride: 108 / 60 (bank-clean)
    constexpr int VEC = (K == 100) ? 4 : 2;   // A rows: 400B -> 16B chunks, 200B -> 8B
    constexpr int CHUNKS = K / VEC;      // 25 per row, both layers
    extern __shared__ uint32_t smu[];
    uint32_t* sW = smu;                  // [KP][NW]
    uint32_t* sA = smu + KP * NW;        // [128][KS]
    const float* A = (L == 1) ? A_in : g_h;

    int tid = threadIdx.x;
    int target = (L == 1) ? *targetPtr : -1;

    // stage W once (tf32 bits via cvt.rna; zero padding)
    for (int idx = tid; idx < KP * NW; idx += 512) {
        int k = idx / NW, c = idx - k * NW;
        float v = 0.f;
        if (k < K && c < 300) {
            if (c < 50) v = rootW[k * DHID + c];
            else { int b = (c - 50) / 50, j = (c - 50) - b * 50;
                   v = basisW[((size_t)b * K + k) * DHID + j]; }
        }
        sW[idx] = f2tf32(v);
    }
    // zero the A pad columns once (staging never touches them)
    for (int idx = tid; idx < 128 * (KS - K); idx += 512) {
        int i = idx / (KS - K), k = K + idx - i * (KS - K);
        sA[i * KS + k] = 0u;
    }

    int lane = tid & 31, warp = tid >> 5;
    int gid = lane >> 2, tig = lane & 3;
    int rg = warp >> 1, nh = warp & 1;
    int wr = rg * 16;

    // async-stage one 128-row tile (raw f32 bits)
    auto stage_tile = [&](int t) {
        int n0 = t * 128;
        for (int idx = tid; idx < 128 * CHUNKS; idx += 512) {
            int i = idx / CHUNKS, q = idx - i * CHUNKS;
            int n = n0 + i;
            bool ok = (n < NN) && (n != target);
            const float* src = A + (ok ? ((size_t)n * K + q * VEC) : 0);
            uint32_t dst = smem_u32(&sA[i * KS + q * VEC]);
            if (VEC == 4) cpa16(dst, src, ok);
            else          cpa8(dst, src, ok);
        }
        cpa_commit();
    };

    stage_tile(blockIdx.x);   // prologue

    for (int t = blockIdx.x; t < NT128; t += gridDim.x) {
        cpa_wait0();
        __syncthreads();       // tile data visible to all warps (also fences W, iter 0)

        // A fragments for this warp's 16 rows, all k-tiles
        uint32_t aF[KT][4];
#pragma unroll
        for (int kt = 0; kt < KT; kt++) {
            int r0 = (wr + gid) * KS, r1 = (wr + gid + 8) * KS;
            int kk = kt * 8 + tig;
            aF[kt][0] = sA[r0 + kk];
            aF[kt][1] = sA[r1 + kk];
            aF[kt][2] = sA[r0 + kk + 4];
            aF[kt][3] = sA[r1 + kk + 4];
        }
        __syncthreads();       // all warps hold frags; sA may be overwritten

        int tn = t + gridDim.x;
        if (tn < NT128) stage_tile(tn);   // overlaps the compute below

        int n0 = t * 128;
        int nrow0 = n0 + wr + gid;
        int nrow1 = nrow0 + 8;
        // n-pairs q=0..18 (pair q covers n-tiles 2q, 2q+1); half nh takes q%2==nh
        for (int q = nh; q < 19; q += 2) {
            int nt = 2 * q;
            float c0[4] = {0.f, 0.f, 0.f, 0.f};
            float c1[4] = {0.f, 0.f, 0.f, 0.f};
            int nb = nt * 8 + gid;
#pragma unroll
            for (int kt = 0; kt < KT; kt++) {
                int kb = kt * 8 + tig;
                uint32_t b0a = sW[kb * NW + nb];
                uint32_t b1a = sW[(kb + 4) * NW + nb];
                uint32_t b0b = sW[kb * NW + nb + 8];
                uint32_t b1b = sW[(kb + 4) * NW + nb + 8];
                mma_tf32(c0, aF[kt], b0a, b1a);
                mma_tf32(c1, aF[kt], b0b, b1b);
            }
            int colA = nt * 8 + tig * 2;       // even
            int colB = colA + 8;
            if (nrow0 < NN) {
                store_pair<L>(nrow0, colA, c0[0], c0[1]);
                if (colB < 300) store_pair<L>(nrow0, colB, c1[0], c1[1]);
            }
            if (nrow1 < NN) {
                store_pair<L>(nrow1, colA, c0[2], c0[3]);
                if (colB < 300) store_pair<L>(nrow1, colB, c1[2], c1[3]);
            }
        }
    }
}

// ---------------- per-edge accumulate helper ----------------
template <int L>
__device__ __forceinline__ void edge_acc(int2 st, int lane, float2& acc) {
    const float*   T  = (L == 1) ? g_T1  : g_T2;
    const __half2* XB = (L == 1) ? g_XB1h : g_XB2h;
    const float4*  C4 = (L == 1) ? g_c4a : g_c4b;
    const float*   C1 = (L == 1) ? g_c1a : g_c1b;
    float4 c  = __ldg(&C4[st.y]);
    float  c4 = __ldg(&C1[st.y]);
    float2 tv = __ldg(((const float2*)(T + st.y * DHID)) + lane);
    const __half2* xr = XB + (size_t)st.x * 125;
    float2 v0 = __half22float2(__ldg(xr + lane));
    float2 v1 = __half22float2(__ldg(xr + 25 + lane));
    float2 v2 = __half22float2(__ldg(xr + 50 + lane));
    float2 v3 = __half22float2(__ldg(xr + 75 + lane));
    float2 v4 = __half22float2(__ldg(xr + 100 + lane));
    acc.x += tv.x; acc.y += tv.y;
    acc.x = fmaf(c.x, v0.x, acc.x); acc.y = fmaf(c.x, v0.y, acc.y);
    acc.x = fmaf(c.y, v1.x, acc.x); acc.y = fmaf(c.y, v1.y, acc.y);
    acc.x = fmaf(c.z, v2.x, acc.x); acc.y = fmaf(c.z, v2.y, acc.y);
    acc.x = fmaf(c.w, v3.x, acc.x); acc.y = fmaf(c.w, v3.y, acc.y);
    acc.x = fmaf(c4,  v4.x, acc.x); acc.y = fmaf(c4,  v4.y, acc.y);
}

// ---------------- aggregation: warp per node over CSR, atomic-free, 4-edge unroll --
template <int L>
__global__ void k_agg(const float* __restrict__ bias, float* __restrict__ out) {
    int n = (blockIdx.x * blockDim.x + threadIdx.x) >> 5;
    if (n >= NN) return;
    int lane = threadIdx.x & 31;
    int end = g_woff[n];          // row end after scatter
    int d = g_deg[n];
    int start = end - d;

    float2 a0 = make_float2(0.f, 0.f), a1 = a0, a2 = a0, a3 = a0;
    int e = start;
    for (; e + 3 < end; e += 4) {
        int2 s0 = __ldg(&g_st[e]);
        int2 s1 = __ldg(&g_st[e + 1]);
        int2 s2 = __ldg(&g_st[e + 2]);
        int2 s3 = __ldg(&g_st[e + 3]);
        if (lane < 25) {
            edge_acc<L>(s0, lane, a0);
            edge_acc<L>(s1, lane, a1);
            edge_acc<L>(s2, lane, a2);
            edge_acc<L>(s3, lane, a3);
        }
    }
    for (; e < end; e++) {
        int2 s0 = __ldg(&g_st[e]);
        if (lane < 25) edge_acc<L>(s0, lane, a0);
    }
    float2 acc = make_float2(a0.x + a1.x + a2.x + a3.x, a0.y + a1.y + a2.y + a3.y);

    float cn = fmaxf((float)d, 1.0f);
    if (L == 1) {
        if (lane < 25) {
            float2 r  = __ldg(((const float2*)(g_rt1 + (size_t)n * DHID)) + lane);
            float2 bb = __ldg(((const float2*)bias) + lane);
            ((float2*)(g_h + (size_t)n * DHID))[lane] =
                make_float2(acc.x / cn + r.x + bb.x, acc.y / cn + r.y + bb.y);
        }
    } else {
        float vx = -1e30f, vy = -1e30f;
        if (lane < 25) {
            float2 r  = __ldg(((const float2*)(g_rt2 + (size_t)n * DHID)) + lane);
            float2 bb = __ldg(((const float2*)bias) + lane);
            vx = acc.x / cn + r.x + bb.x;
            vy = acc.y / cn + r.y + bb.y;
        }
        float m = fmaxf(vx, vy);
#pragma unroll
        for (int o = 16; o > 0; o >>= 1) m = fmaxf(m, __shfl_xor_sync(0xFFFFFFFFu, m, o));
        float sacc = (lane < 25) ? (expf(vx - m) + expf(vy - m)) : 0.f;
#pragma unroll
        for (int o = 16; o > 0; o >>= 1) sacc += __shfl_xor_sync(0xFFFFFFFFu, sacc, o);
        float ls = logf(sacc);
        if (lane < 25)
            ((float2*)(out + (size_t)n * DHID))[lane] = make_float2(vx - m - ls, vy - m - ls);
    }
}

// ---------------- launcher ----------------
extern "C" void kernel_launch(void* const* d_in, const int* in_sizes, int n_in,
                              void* d_out, int out_size) {
    const float* x      = (const float*)d_in[0];
    const int*   ei     = (const int*)d_in[1];
    const int*   etype  = (const int*)d_in[2];
    const int*   tgt    = (const int*)d_in[3];
    const float* relE   = (const float*)d_in[4];
    const float* relW   = (const float*)d_in[5];
    const float* basis1 = (const float*)d_in[6];
    const float* comp1  = (const float*)d_in[7];
    const float* root1  = (const float*)d_in[8];
    const float* bias1  = (const float*)d_in[9];
    const float* basis2 = (const float*)d_in[10];
    const float* comp2  = (const float*)d_in[11];
    const float* root2  = (const float*)d_in[12];
    const float* bias2  = (const float*)d_in[13];
    float* out = (float*)d_out;
    int E = in_sizes[1] / 2;

    constexpr int SM1 = (104 * NW + 128 * 108) * (int)sizeof(uint32_t);  // 185,088 B
    constexpr int SM2 = (56 * NW + 128 * 60) * (int)sizeof(uint32_t);    // 100,608 B
    cudaFuncSetAttribute(k_gemm_t<DIN, 1>, cudaFuncAttributeMaxDynamicSharedMemorySize, SM1);
    cudaFuncSetAttribute(k_gemm_t<DHID, 2>, cudaFuncAttributeMaxDynamicSharedMemorySize, SM2);

    // launch order chosen so the profiler's sampled launch (index 3) is gemm1
    k_zero<<<(NN + 255) / 256, 256>>>();                       // 0
    k_hist<<<(E + 255) / 256, 256>>>(ei, E);                   // 1
    k_tables<<<NRT, 64>>>(relE, relW, basis1, comp1, basis2, comp2);  // 2
    k_gemm_t<DIN, 1><<<148, 512, SM1>>>(x, basis1, root1, tgt);       // 3 <- profiled
    k_scan1<<<NCH, SCAN_CH>>>();                               // 4
    k_scan2<<<1, 256>>>();                                     // 5
    k_scan3<<<(NN + 255) / 256, 256>>>();                      // 6
    k_scatter<<<(E + 255) / 256, 256>>>(ei, etype, E);         // 7
    k_agg<1><<<(NN + 7) / 8, 256>>>(bias1, nullptr);           // 8
    k_gemm_t<DHID, 2><<<296, 512, SM2>>>(x /*unused*/, basis2, root2, nullptr);  // 9
    k_agg<2><<<(NN + 7) / 8, 256>>>(bias2, out);               // 10
}